// round 11
// baseline (speedup 1.0000x reference)
#include <cuda_runtime.h>
#include <cuda_fp16.h>
#include <math.h>
#include <stdint.h>

#define B_ 8
#define C_ 512
#define H_ 2048
#define G_ 32
#define CPG 16
static const long CH  = (long)C_ * H_;
static const long CH3 = 3 * (long)C_ * H_;

// Scratch (device globals: allocation-free contract). fp16 intermediates.
__device__ __half g_hn [B_*C_*H_];        // GN output; later reused for attn*V output
__device__ __half g_qkv[B_*3*C_*H_];      // fused q/k/v: [b][3C][H]
__device__ __half g_s  [(long)B_*H_*H_];  // attention exp-scores (64 MB fp16)
__device__ __half g_w  [3*C_*C_];         // fused fp16 weights: wq,wk,wv stacked
__device__ __half g_wp [C_*C_];           // fp16 proj weight
__device__ float  g_bias[3*C_];           // fused q/k/v bias
__device__ float  g_rsum[B_*H_];          // softmax row sums (of exp(x-8))

__device__ __forceinline__ uint32_t smem_u32(const void* p) {
    return (uint32_t)__cvta_generic_to_shared(p);
}
__device__ __forceinline__ void st_h4(__half* dst, float4 v) {
    __half2 lo = __floats2half2_rn(v.x, v.y);
    __half2 hi = __floats2half2_rn(v.z, v.w);
    uint2 u;
    u.x = *reinterpret_cast<uint32_t*>(&lo);
    u.y = *reinterpret_cast<uint32_t*>(&hi);
    *reinterpret_cast<uint2*>(dst) = u;
}

// ---------------------------------------------------------------------------
// Weight fp32 -> fp16 (wq|wk|wv stacked, wp separate), bias concat, rsum zero
// ---------------------------------------------------------------------------
__global__ __launch_bounds__(256) void w2h_kernel(const float* __restrict__ wq,
                                                  const float* __restrict__ wk,
                                                  const float* __restrict__ wv,
                                                  const float* __restrict__ wp,
                                                  const float* __restrict__ bq,
                                                  const float* __restrict__ bk,
                                                  const float* __restrict__ bv)
{
    const int gid = blockIdx.x * 256 + threadIdx.x;   // 262144 threads
    if (gid < B_ * H_) g_rsum[gid] = 0.f;
    if (gid < 3 * C_) {
        const float* b = (gid < C_) ? bq : (gid < 2*C_) ? bk : bv;
        g_bias[gid] = b[gid & (C_ - 1)];
    }
    const int mat = gid >> 16;                        // C*C/4 = 65536 float4s per matrix
    const int off = (gid & 65535) * 4;
    if (mat < 3) {
        const float* src = (mat == 0) ? wq : (mat == 1) ? wk : wv;
        float4 v = *reinterpret_cast<const float4*>(src + off);
        st_h4(&g_w[(long)mat * C_ * C_ + off], v);
    } else {
        float4 v = *reinterpret_cast<const float4*>(wp + off);
        st_h4(&g_wp[off], v);
    }
}

// ---------------------------------------------------------------------------
// GroupNorm -> fp16 output
// ---------------------------------------------------------------------------
__global__ __launch_bounds__(256) void gn_kernel(const float* __restrict__ x,
                                                 const float* __restrict__ gamma,
                                                 const float* __restrict__ beta,
                                                 __half* __restrict__ hn)
{
    const int b = blockIdx.x >> 5;
    const int g = blockIdx.x & 31;
    const long base = ((long)b * C_ + (long)g * CPG) * H_;
    const float4* xp = reinterpret_cast<const float4*>(x + base);
    const int NE4 = CPG * H_ / 4;
    const int tid = threadIdx.x;

    float s = 0.f, ss = 0.f;
    for (int i = tid; i < NE4; i += 256) {
        float4 v = xp[i];
        s  += v.x + v.y + v.z + v.w;
        ss += v.x*v.x + v.y*v.y + v.z*v.z + v.w*v.w;
    }
    __shared__ float rs[8], rss[8];
    #pragma unroll
    for (int o = 16; o > 0; o >>= 1) {
        s  += __shfl_down_sync(0xFFFFFFFFu, s,  o);
        ss += __shfl_down_sync(0xFFFFFFFFu, ss, o);
    }
    if ((tid & 31) == 0) { rs[tid >> 5] = s; rss[tid >> 5] = ss; }
    __syncthreads();
    if (tid < 32) {
        s  = (tid < 8) ? rs[tid]  : 0.f;
        ss = (tid < 8) ? rss[tid] : 0.f;
        #pragma unroll
        for (int o = 4; o > 0; o >>= 1) {
            s  += __shfl_down_sync(0xFFFFFFFFu, s,  o);
            ss += __shfl_down_sync(0xFFFFFFFFu, ss, o);
        }
        if (tid == 0) { rs[0] = s; rss[0] = ss; }
    }
    __syncthreads();
    const float mean = rs[0] * (1.f / (CPG * H_));
    const float var  = rss[0] * (1.f / (CPG * H_)) - mean * mean;
    const float inv  = rsqrtf(var + 1e-6f);

    for (int i = tid; i < NE4; i += 256) {
        const int c = g * CPG + (i * 4) / H_;
        const float gm = gamma[c] * inv;
        const float bt = beta[c] - mean * gm;
        float4 v = xp[i];
        float4 o;
        o.x = v.x * gm + bt; o.y = v.y * gm + bt;
        o.z = v.z * gm + bt; o.w = v.w * gm + bt;
        st_h4(&hn[base + (long)i * 4], o);
    }
}

// ---------------------------------------------------------------------------
// Tensor-core fp16 GEMM, XOR-swizzled smem, BK=64, 3 stages,
// ks fragment double-buffering + strength-reduced addressing.
//   C[m,n] = alpha * sum_k A(m,k)*B(k,n) (+bias[m]) (+resid fp32)
//   EXPSUM: out = exp(alpha*acc - 8), atomic row-sum into rsum[bz*H+m]
//   RSCALE: out *= 1/rsum[bz*H + n]
// ---------------------------------------------------------------------------
#define BM 128
#define BN 128
#define BK 64
#define NSTAGE 3
#define STG_BYTES 32768
#define GEMM_SMEM (NSTAGE * STG_BYTES)

__device__ __forceinline__ void cp16(uint32_t s, const void* g) {
    asm volatile("cp.async.cg.shared.global [%0], [%1], 16;" :: "r"(s), "l"(g));
}
__device__ __forceinline__ void cp_commit() { asm volatile("cp.async.commit_group;"); }
__device__ __forceinline__ void cp_wait1() { asm volatile("cp.async.wait_group 1;"); }
__device__ __forceinline__ void cp_wait0() { asm volatile("cp.async.wait_group 0;"); }

__device__ __forceinline__ void ldsm4(uint32_t* r, uint32_t a) {
    asm volatile("ldmatrix.sync.aligned.m8n8.x4.shared.b16 {%0,%1,%2,%3}, [%4];"
                 : "=r"(r[0]), "=r"(r[1]), "=r"(r[2]), "=r"(r[3]) : "r"(a));
}
__device__ __forceinline__ void ldsm4t(uint32_t* r, uint32_t a) {
    asm volatile("ldmatrix.sync.aligned.m8n8.x4.trans.shared.b16 {%0,%1,%2,%3}, [%4];"
                 : "=r"(r[0]), "=r"(r[1]), "=r"(r[2]), "=r"(r[3]) : "r"(a));
}
__device__ __forceinline__ void mma16816(float* c, const uint32_t* a, const uint32_t* b) {
    asm volatile("mma.sync.aligned.m16n8k16.row.col.f32.f16.f16.f32 "
                 "{%0,%1,%2,%3}, {%4,%5,%6,%7}, {%8,%9}, {%0,%1,%2,%3};"
                 : "+f"(c[0]), "+f"(c[1]), "+f"(c[2]), "+f"(c[3])
                 : "r"(a[0]), "r"(a[1]), "r"(a[2]), "r"(a[3]), "r"(b[0]), "r"(b[1]));
}
__device__ __forceinline__ void store2(float* p, float x, float y) {
    *reinterpret_cast<float2*>(p) = make_float2(x, y);
}
__device__ __forceinline__ void store2(__half* p, float x, float y) {
    *reinterpret_cast<__half2*>(p) = __floats2half2_rn(x, y);
}

template<bool TA, bool TB, typename OutT, bool EXPSUM, bool RSCALE>
__global__ __launch_bounds__(256) void hgemm_kernel(
    const __half* __restrict__ Ab, const __half* __restrict__ Bb, OutT* __restrict__ Cb,
    int K, int lda, int ldb, int ldc,
    long sA, long sB, long sC,
    const float* __restrict__ bias, float alpha,
    const float* __restrict__ resid, long sR,
    float* __restrict__ rsum)
{
    extern __shared__ __align__(128) char sm[];
    const uint32_t smb = smem_u32(sm);

    const int tid = threadIdx.x;
    const int bz = blockIdx.z;
    const __half* A = Ab + (long)bz * sA;
    const __half* B = Bb + (long)bz * sB;
    OutT* C = Cb + (long)bz * sC;
    const int m0 = blockIdx.y * BM;
    const int n0 = blockIdx.x * BN;

    const int wid = tid >> 5, lane = tid & 31;
    const int wm = (wid & 1) * 64;
    const int wn = (wid >> 1) * 32;

    float acc[4][4][4] = {};

    auto stage = [&](int k0, int buf) {
        const uint32_t ab = smb + buf * STG_BYTES;
        const uint32_t bb = ab + 16384;
        #pragma unroll
        for (int i = 0; i < 4; i++) {
            const int c = tid + i * 256;
            if (!TA) {
                const int row = c >> 3, ch = c & 7;
                const int sw = ch ^ (row & 7);
                cp16(ab + row * 128 + sw * 16,
                     &A[(long)(m0 + row) * lda + k0 + ch * 8]);
            } else {
                const int row = c >> 4, ch = c & 15;
                const int sw = (ch & 8) | ((ch ^ row) & 7);
                cp16(ab + row * 256 + sw * 16,
                     &A[(long)(k0 + row) * lda + m0 + ch * 8]);
            }
        }
        #pragma unroll
        for (int i = 0; i < 4; i++) {
            const int c = tid + i * 256;
            if (!TB) {
                const int row = c >> 4, ch = c & 15;
                const int sw = (ch & 8) | ((ch ^ row) & 7);
                cp16(bb + row * 256 + sw * 16,
                     &B[(long)(k0 + row) * ldb + n0 + ch * 8]);
            } else {
                const int row = c >> 3, ch = c & 7;
                const int sw = ch ^ (row & 7);
                cp16(bb + row * 128 + sw * 16,
                     &B[(long)(n0 + row) * ldb + k0 + ch * 8]);
            }
        }
        cp_commit();
    };

    // Per-ks fragment addresses via strength reduction:
    //   128B-row layouts: addr(ks) = base ^ (ks*2)
    //   256B-row layouts: addr(ks) = base + ks*256
    auto load_frags = [&](int ks, uint32_t a[4][4], uint32_t b[4][2],
                          const uint32_t baA[4], const uint32_t baB[2]) {
        #pragma unroll
        for (int mt = 0; mt < 4; mt++) {
            const uint32_t addr = TA ? (baA[mt] + ks * 256) : (baA[mt] ^ (ks * 2));
            if (!TA) ldsm4(a[mt], addr);
            else     ldsm4t(a[mt], addr);
        }
        #pragma unroll
        for (int nt2 = 0; nt2 < 2; nt2++) {
            uint32_t r[4];
            const uint32_t addr = (!TB) ? (baB[nt2] + ks * 256) : (baB[nt2] ^ (ks * 2));
            if (!TB) ldsm4t(r, addr);
            else     ldsm4(r, addr);
            b[2*nt2][0] = r[0]; b[2*nt2][1] = r[1];
            b[2*nt2+1][0] = r[2]; b[2*nt2+1][1] = r[3];
        }
    };

    stage(0, 0);
    stage(BK, 1);

    const int T = K / BK;
    for (int t = 0; t < T; t++) {
        cp_wait1();
        __syncthreads();
        if (t + 2 < T) stage((t + 2) * BK, (t + 2) % NSTAGE);

        const uint32_t ab = smb + (t % NSTAGE) * STG_BYTES;
        const uint32_t bb = ab + 16384;

        // ---- per-k-tile fragment base addresses ----
        uint32_t baA[4], baB[2];
        #pragma unroll
        for (int mt = 0; mt < 4; mt++) {
            if (!TA) {
                const int row = wm + mt * 16 + (lane & 15);
                const int hi = lane >> 4;
                baA[mt] = ab + row * 128 + ((hi ^ (row & 7)) << 4);
            } else {
                const int kk0 = (lane >> 4) * 8 + (lane & 7);
                const int mm = wm + mt * 16 + ((lane >> 3) & 1) * 8;
                const int ch = mm >> 3;
                const int sw = (ch & 8) | ((ch ^ kk0) & 7);
                baA[mt] = ab + kk0 * 256 + sw * 16;
            }
        }
        #pragma unroll
        for (int nt2 = 0; nt2 < 2; nt2++) {
            if (!TB) {
                const int kk0 = ((lane >> 3) & 1) * 8 + (lane & 7);
                const int ncol = wn + nt2 * 16 + ((lane >> 4) & 1) * 8;
                const int ch = ncol >> 3;
                const int sw = (ch & 8) | ((ch ^ kk0) & 7);
                baB[nt2] = bb + kk0 * 256 + sw * 16;
            } else {
                const int nn = wn + nt2 * 16 + ((lane >> 4) & 1) * 8 + (lane & 7);
                const int hi = (lane >> 3) & 1;
                baB[nt2] = bb + nn * 128 + ((hi ^ (nn & 7)) << 4);
            }
        }

        uint32_t fa[2][4][4], fb[2][4][2];
        load_frags(0, fa[0], fb[0], baA, baB);
        #pragma unroll
        for (int s4 = 0; s4 < 4; s4++) {
            const int cur = s4 & 1, nxt = cur ^ 1;
            if (s4 < 3) load_frags((s4 + 1) * 16, fa[nxt], fb[nxt], baA, baB);
            #pragma unroll
            for (int mt = 0; mt < 4; mt++)
                #pragma unroll
                for (int nt = 0; nt < 4; nt++)
                    mma16816(acc[mt][nt], fa[cur][mt], fb[cur][nt]);
        }
    }
    cp_wait0();

    // ---- epilogue ----
    const int r0 = m0 + wm + (lane >> 2);
    const int c0 = n0 + wn + (lane & 3) * 2;
    if (EXPSUM) {
        #pragma unroll
        for (int mt = 0; mt < 4; mt++) {
            #pragma unroll
            for (int h = 0; h < 2; h++) {
                const int rr = r0 + mt * 16 + h * 8;
                float rsl = 0.f;
                #pragma unroll
                for (int nt = 0; nt < 4; nt++) {
                    const float* a4 = acc[mt][nt];
                    float vx = __expf(fmaf(a4[h*2+0], alpha, -8.f));
                    float vy = __expf(fmaf(a4[h*2+1], alpha, -8.f));
                    store2(&C[(long)rr * ldc + c0 + nt * 8], vx, vy);
                    rsl += vx + vy;
                }
                rsl += __shfl_xor_sync(0xFFFFFFFFu, rsl, 1);
                rsl += __shfl_xor_sync(0xFFFFFFFFu, rsl, 2);
                if ((lane & 3) == 0)
                    atomicAdd(&rsum[(long)bz * H_ + rr], rsl);
            }
        }
    } else {
        #pragma unroll
        for (int mt = 0; mt < 4; mt++) {
            #pragma unroll
            for (int nt = 0; nt < 4; nt++) {
                const float* a4 = acc[mt][nt];
                const int c = c0 + nt * 8;
                float sx = 1.f, sy = 1.f;
                if (RSCALE) {
                    sx = 1.f / rsum[(long)bz * H_ + c];
                    sy = 1.f / rsum[(long)bz * H_ + c + 1];
                }
                #pragma unroll
                for (int h = 0; h < 2; h++) {
                    const int rr = r0 + mt * 16 + h * 8;
                    const float bi = bias ? bias[rr] : 0.f;
                    float vx = fmaf(a4[h * 2 + 0], alpha, bi) * sx;
                    float vy = fmaf(a4[h * 2 + 1], alpha, bi) * sy;
                    const long off = (long)rr * ldc + c;
                    if (resid) {
                        const float2 rv = *reinterpret_cast<const float2*>(&resid[(long)bz * sR + off]);
                        vx += rv.x; vy += rv.y;
                    }
                    store2(&C[off], vx, vy);
                }
            }
        }
    }
}

// ---------------------------------------------------------------------------
extern "C" void kernel_launch(void* const* d_in, const int* in_sizes, int n_in,
                              void* d_out, int out_size)
{
    const float* x     = (const float*)d_in[0];
    const float* gamma = (const float*)d_in[1];
    const float* beta  = (const float*)d_in[2];
    const float* wq    = (const float*)d_in[3];
    const float* bq    = (const float*)d_in[4];
    const float* wk    = (const float*)d_in[5];
    const float* bk    = (const float*)d_in[6];
    const float* wv    = (const float*)d_in[7];
    const float* bv    = (const float*)d_in[8];
    const float* wp    = (const float*)d_in[9];
    const float* bp    = (const float*)d_in[10];
    float* out = (float*)d_out;

    __half *hn, *qkv, *s, *w, *wph;
    float *rsum, *biasf;
    cudaGetSymbolAddress((void**)&hn,  g_hn);
    cudaGetSymbolAddress((void**)&qkv, g_qkv);
    cudaGetSymbolAddress((void**)&s,   g_s);
    cudaGetSymbolAddress((void**)&w,   g_w);
    cudaGetSymbolAddress((void**)&wph, g_wp);
    cudaGetSymbolAddress((void**)&rsum, g_rsum);
    cudaGetSymbolAddress((void**)&biasf, g_bias);

    const long HH = (long)H_ * H_;
    const float scale = 0.044194173824159216f;   // 1/sqrt(512)

    cudaFuncSetAttribute((const void*)hgemm_kernel<false, false, __half, false, false>, cudaFuncAttributeMaxDynamicSharedMemorySize, GEMM_SMEM);
    cudaFuncSetAttribute((const void*)hgemm_kernel<false, false, float,  false, false>, cudaFuncAttributeMaxDynamicSharedMemorySize, GEMM_SMEM);
    cudaFuncSetAttribute((const void*)hgemm_kernel<true,  false, __half, true,  false>, cudaFuncAttributeMaxDynamicSharedMemorySize, GEMM_SMEM);
    cudaFuncSetAttribute((const void*)hgemm_kernel<false, true,  __half, false, true >, cudaFuncAttributeMaxDynamicSharedMemorySize, GEMM_SMEM);

    // 0. weights -> fp16 (+ bias concat + zero rsum) ; 1. GroupNorm -> fp16
    w2h_kernel<<<1024, 256>>>(wq, wk, wv, wp, bq, bk, bv);
    gn_kernel<<<B_ * G_, 256>>>(x, gamma, beta, hn);

    // 2. fused qkv = Wqkv[1536x512] @ hn_b + bias  -> g_qkv [b][3C][H]
    dim3 gqkv(H_ / BN, 3 * C_ / BM, B_);
    hgemm_kernel<false, false, __half, false, false><<<gqkv, 256, GEMM_SMEM>>>(
        w, hn, qkv, C_, C_, H_, H_, 0, CH, CH3, biasf, 1.f, nullptr, 0, nullptr);

    // 3. P[b,i,j] = exp(scale * sum_c q[b,c,i] k[b,c,j] - 8), rowsum -> rsum
    const __half* qp = qkv;            // channels [0,C)
    const __half* kp = qkv + CH;       // channels [C,2C)
    const __half* vp = qkv + 2 * CH;   // channels [2C,3C)
    dim3 gsc(H_ / BN, H_ / BM, B_);
    hgemm_kernel<true, false, __half, true, false><<<gsc, 256, GEMM_SMEM>>>(
        qp, kp, s, C_, H_, H_, H_, CH3, CH3, HH, nullptr, scale, nullptr, 0, rsum);

    // 4. h_[b,c,i] = (1/rsum[i]) * sum_j v[b,c,j] P[i,j]   (A=[m,k], B=[n,k])
    dim3 gav(H_ / BN, C_ / BM, B_);
    hgemm_kernel<false, true, __half, false, true><<<gav, 256, GEMM_SMEM>>>(
        vp, s, hn, H_, H_, H_, H_, CH3, HH, CH, nullptr, 1.f, nullptr, 0, rsum);

    // 5. out = x + Wp @ h_ + bp  (fp32 out, residual)
    dim3 gpr(H_ / BN, C_ / BM, B_);
    hgemm_kernel<false, false, float, false, false><<<gpr, 256, GEMM_SMEM>>>(
        wph, hn, out, C_, C_, H_, H_, 0, CH, CH, bp, 1.f, x, CH, nullptr);
}

// round 12
// speedup vs baseline: 1.0083x; 1.0083x over previous
#include <cuda_runtime.h>
#include <cuda_fp16.h>
#include <math.h>
#include <stdint.h>

#define B_ 8
#define C_ 512
#define H_ 2048
#define G_ 32
#define CPG 16
static const long CH = (long)C_ * H_;

// Scratch (device globals: allocation-free contract). All fp16 intermediates.
__device__ __half g_hn[B_*C_*H_];        // GN output; later reused for attn*V output
__device__ __half g_q [B_*C_*H_];
__device__ __half g_k [B_*C_*H_];
__device__ __half g_v [B_*C_*H_];
__device__ __half g_s [(long)B_*H_*H_]; // attention exp-scores (64 MB fp16)
__device__ __half g_w [4*C_*C_];        // fp16 weights: wq,wk,wv,wp
__device__ float  g_rsum[B_*H_];        // softmax row sums (of exp(x-8))

__device__ __forceinline__ uint32_t smem_u32(const void* p) {
    return (uint32_t)__cvta_generic_to_shared(p);
}
__device__ __forceinline__ void st_h4(__half* dst, float4 v) {
    __half2 lo = __floats2half2_rn(v.x, v.y);
    __half2 hi = __floats2half2_rn(v.z, v.w);
    uint2 u;
    u.x = *reinterpret_cast<uint32_t*>(&lo);
    u.y = *reinterpret_cast<uint32_t*>(&hi);
    *reinterpret_cast<uint2*>(dst) = u;
}

// ---------------------------------------------------------------------------
// Weight fp32 -> fp16 conversion (4 x 512 x 512) + zero rsum
// ---------------------------------------------------------------------------
__global__ __launch_bounds__(256) void w2h_kernel(const float* __restrict__ wq,
                                                  const float* __restrict__ wk,
                                                  const float* __restrict__ wv,
                                                  const float* __restrict__ wp,
                                                  __half* __restrict__ dst)
{
    const int gid = blockIdx.x * 256 + threadIdx.x;
    if (gid < B_ * H_) g_rsum[gid] = 0.f;
    const int mat = gid >> 16;
    const int off = (gid & 65535) * 4;
    const float* src = (mat == 0) ? wq : (mat == 1) ? wk : (mat == 2) ? wv : wp;
    float4 v = *reinterpret_cast<const float4*>(src + off);
    st_h4(&dst[(long)mat * C_ * C_ + off], v);
}

// ---------------------------------------------------------------------------
// GroupNorm -> fp16 output
// ---------------------------------------------------------------------------
__global__ __launch_bounds__(256) void gn_kernel(const float* __restrict__ x,
                                                 const float* __restrict__ gamma,
                                                 const float* __restrict__ beta,
                                                 __half* __restrict__ hn)
{
    const int b = blockIdx.x >> 5;
    const int g = blockIdx.x & 31;
    const long base = ((long)b * C_ + (long)g * CPG) * H_;
    const float4* xp = reinterpret_cast<const float4*>(x + base);
    const int NE4 = CPG * H_ / 4;
    const int tid = threadIdx.x;

    float s = 0.f, ss = 0.f;
    for (int i = tid; i < NE4; i += 256) {
        float4 v = xp[i];
        s  += v.x + v.y + v.z + v.w;
        ss += v.x*v.x + v.y*v.y + v.z*v.z + v.w*v.w;
    }
    __shared__ float rs[8], rss[8];
    #pragma unroll
    for (int o = 16; o > 0; o >>= 1) {
        s  += __shfl_down_sync(0xFFFFFFFFu, s,  o);
        ss += __shfl_down_sync(0xFFFFFFFFu, ss, o);
    }
    if ((tid & 31) == 0) { rs[tid >> 5] = s; rss[tid >> 5] = ss; }
    __syncthreads();
    if (tid < 32) {
        s  = (tid < 8) ? rs[tid]  : 0.f;
        ss = (tid < 8) ? rss[tid] : 0.f;
        #pragma unroll
        for (int o = 4; o > 0; o >>= 1) {
            s  += __shfl_down_sync(0xFFFFFFFFu, s,  o);
            ss += __shfl_down_sync(0xFFFFFFFFu, ss, o);
        }
        if (tid == 0) { rs[0] = s; rss[0] = ss; }
    }
    __syncthreads();
    const float mean = rs[0] * (1.f / (CPG * H_));
    const float var  = rss[0] * (1.f / (CPG * H_)) - mean * mean;
    const float inv  = rsqrtf(var + 1e-6f);

    for (int i = tid; i < NE4; i += 256) {
        const int c = g * CPG + (i * 4) / H_;
        const float gm = gamma[c] * inv;
        const float bt = beta[c] - mean * gm;
        float4 v = xp[i];
        float4 o;
        o.x = v.x * gm + bt; o.y = v.y * gm + bt;
        o.z = v.z * gm + bt; o.w = v.w * gm + bt;
        st_h4(&hn[base + (long)i * 4], o);
    }
}

// ---------------------------------------------------------------------------
// Tensor-core fp16 GEMM, XOR-swizzled smem, BK=64, 3 stages,
// ks-level fragment double-buffering.
//   C[m,n] = alpha * sum_k A(m,k)*B(k,n) (+bias[m]) (+resid fp32)
//   EXPSUM: out = exp2(alpha*acc - 8*log2e)  [alpha pre-scaled by log2e],
//           atomic row-sum into rsum[bz*H+m]
//   RSCALE: out *= 1/rsum[bz*H + n]
// ---------------------------------------------------------------------------
#define BM 128
#define BN 128
#define BK 64
#define NSTAGE 3
#define STG_BYTES 32768
#define GEMM_SMEM (NSTAGE * STG_BYTES)

__device__ __forceinline__ void cp16(uint32_t s, const void* g) {
    asm volatile("cp.async.cg.shared.global [%0], [%1], 16;" :: "r"(s), "l"(g));
}
__device__ __forceinline__ void cp_commit() { asm volatile("cp.async.commit_group;"); }
__device__ __forceinline__ void cp_wait1() { asm volatile("cp.async.wait_group 1;"); }
__device__ __forceinline__ void cp_wait0() { asm volatile("cp.async.wait_group 0;"); }

__device__ __forceinline__ void ldsm4(uint32_t* r, uint32_t a) {
    asm volatile("ldmatrix.sync.aligned.m8n8.x4.shared.b16 {%0,%1,%2,%3}, [%4];"
                 : "=r"(r[0]), "=r"(r[1]), "=r"(r[2]), "=r"(r[3]) : "r"(a));
}
__device__ __forceinline__ void ldsm4t(uint32_t* r, uint32_t a) {
    asm volatile("ldmatrix.sync.aligned.m8n8.x4.trans.shared.b16 {%0,%1,%2,%3}, [%4];"
                 : "=r"(r[0]), "=r"(r[1]), "=r"(r[2]), "=r"(r[3]) : "r"(a));
}
__device__ __forceinline__ void mma16816(float* c, const uint32_t* a, const uint32_t* b) {
    asm volatile("mma.sync.aligned.m16n8k16.row.col.f32.f16.f16.f32 "
                 "{%0,%1,%2,%3}, {%4,%5,%6,%7}, {%8,%9}, {%0,%1,%2,%3};"
                 : "+f"(c[0]), "+f"(c[1]), "+f"(c[2]), "+f"(c[3])
                 : "r"(a[0]), "r"(a[1]), "r"(a[2]), "r"(a[3]), "r"(b[0]), "r"(b[1]));
}
__device__ __forceinline__ void store2(float* p, float x, float y) {
    *reinterpret_cast<float2*>(p) = make_float2(x, y);
}
__device__ __forceinline__ void store2(__half* p, float x, float y) {
    *reinterpret_cast<__half2*>(p) = __floats2half2_rn(x, y);
}

template<bool TA, bool TB, typename OutT, bool EXPSUM, bool RSCALE>
__global__ __launch_bounds__(256) void hgemm_kernel(
    const __half* __restrict__ Ab, const __half* __restrict__ Bb, OutT* __restrict__ Cb,
    int K, int lda, int ldb, int ldc,
    long sA, long sB, long sC,
    const float* __restrict__ bias, float alpha,
    const float* __restrict__ resid, long sR,
    float* __restrict__ rsum)
{
    extern __shared__ __align__(128) char sm[];
    const uint32_t smb = smem_u32(sm);

    const int tid = threadIdx.x;
    const int bz = blockIdx.z;
    const __half* A = Ab + (long)bz * sA;
    const __half* B = Bb + (long)bz * sB;
    OutT* C = Cb + (long)bz * sC;
    const int m0 = blockIdx.y * BM;
    const int n0 = blockIdx.x * BN;

    const int wid = tid >> 5, lane = tid & 31;
    const int wm = (wid & 1) * 64;
    const int wn = (wid >> 1) * 32;

    float acc[4][4][4] = {};

    auto stage = [&](int k0, int buf) {
        const uint32_t ab = smb + buf * STG_BYTES;
        const uint32_t bb = ab + 16384;
        #pragma unroll
        for (int i = 0; i < 4; i++) {
            const int c = tid + i * 256;
            if (!TA) {
                const int row = c >> 3, ch = c & 7;
                const int sw = ch ^ (row & 7);
                cp16(ab + row * 128 + sw * 16,
                     &A[(long)(m0 + row) * lda + k0 + ch * 8]);
            } else {
                const int row = c >> 4, ch = c & 15;
                const int sw = (ch & 8) | ((ch ^ row) & 7);
                cp16(ab + row * 256 + sw * 16,
                     &A[(long)(k0 + row) * lda + m0 + ch * 8]);
            }
        }
        #pragma unroll
        for (int i = 0; i < 4; i++) {
            const int c = tid + i * 256;
            if (!TB) {
                const int row = c >> 4, ch = c & 15;
                const int sw = (ch & 8) | ((ch ^ row) & 7);
                cp16(bb + row * 256 + sw * 16,
                     &B[(long)(k0 + row) * ldb + n0 + ch * 8]);
            } else {
                const int row = c >> 3, ch = c & 7;
                const int sw = ch ^ (row & 7);
                cp16(bb + row * 128 + sw * 16,
                     &B[(long)(n0 + row) * ldb + k0 + ch * 8]);
            }
        }
        cp_commit();
    };

    // fragment loader for one ks step (16 wide)
    auto load_frags = [&](int ks, uint32_t a[4][4], uint32_t b[4][2],
                          uint32_t ab, uint32_t bb) {
        #pragma unroll
        for (int mt = 0; mt < 4; mt++) {
            if (!TA) {
                const int row = wm + mt * 16 + (lane & 15);
                const int ch = (ks >> 3) + (lane >> 4);
                const int sw = ch ^ (row & 7);
                ldsm4(a[mt], ab + row * 128 + sw * 16);
            } else {
                const int kk = ks + (lane >> 4) * 8 + (lane & 7);
                const int mm = wm + mt * 16 + ((lane >> 3) & 1) * 8;
                const int ch = mm >> 3;
                const int sw = (ch & 8) | ((ch ^ kk) & 7);
                ldsm4t(a[mt], ab + kk * 256 + sw * 16);
            }
        }
        #pragma unroll
        for (int nt2 = 0; nt2 < 2; nt2++) {
            uint32_t r[4];
            if (!TB) {
                const int kk = ks + ((lane >> 3) & 1) * 8 + (lane & 7);
                const int ncol = wn + nt2 * 16 + ((lane >> 4) & 1) * 8;
                const int ch = ncol >> 3;
                const int sw = (ch & 8) | ((ch ^ kk) & 7);
                ldsm4t(r, bb + kk * 256 + sw * 16);
            } else {
                const int nn = wn + nt2 * 16 + ((lane >> 4) & 1) * 8 + (lane & 7);
                const int ch = (ks >> 3) + ((lane >> 3) & 1);
                const int sw = ch ^ (nn & 7);
                ldsm4(r, bb + nn * 128 + sw * 16);
            }
            b[2*nt2][0] = r[0]; b[2*nt2][1] = r[1];
            b[2*nt2+1][0] = r[2]; b[2*nt2+1][1] = r[3];
        }
    };

    stage(0, 0);
    stage(BK, 1);

    const int T = K / BK;
    for (int t = 0; t < T; t++) {
        cp_wait1();
        __syncthreads();
        if (t + 2 < T) stage((t + 2) * BK, (t + 2) % NSTAGE);

        const uint32_t ab = smb + (t % NSTAGE) * STG_BYTES;
        const uint32_t bb = ab + 16384;

        uint32_t fa[2][4][4], fb[2][4][2];
        load_frags(0, fa[0], fb[0], ab, bb);
        #pragma unroll
        for (int s4 = 0; s4 < 4; s4++) {
            const int cur = s4 & 1, nxt = cur ^ 1;
            if (s4 < 3) load_frags((s4 + 1) * 16, fa[nxt], fb[nxt], ab, bb);
            #pragma unroll
            for (int mt = 0; mt < 4; mt++)
                #pragma unroll
                for (int nt = 0; nt < 4; nt++)
                    mma16816(acc[mt][nt], fa[cur][mt], fb[cur][nt]);
        }
    }
    cp_wait0();

    // ---- epilogue ----
    const int r0 = m0 + wm + (lane >> 2);
    const int c0 = n0 + wn + (lane & 3) * 2;
    if (EXPSUM) {
        // alpha is pre-scaled by log2(e); exp(x-8) = exp2(x*log2e - 8*log2e)
        #pragma unroll
        for (int mt = 0; mt < 4; mt++) {
            #pragma unroll
            for (int h = 0; h < 2; h++) {
                const int rr = r0 + mt * 16 + h * 8;
                float rsl = 0.f;
                #pragma unroll
                for (int nt = 0; nt < 4; nt++) {
                    const float* a4 = acc[mt][nt];
                    float vx = exp2f(fmaf(a4[h*2+0], alpha, -11.541560327111708f));
                    float vy = exp2f(fmaf(a4[h*2+1], alpha, -11.541560327111708f));
                    store2(&C[(long)rr * ldc + c0 + nt * 8], vx, vy);
                    rsl += vx + vy;
                }
                rsl += __shfl_xor_sync(0xFFFFFFFFu, rsl, 1);
                rsl += __shfl_xor_sync(0xFFFFFFFFu, rsl, 2);
                if ((lane & 3) == 0)
                    atomicAdd(&rsum[(long)bz * H_ + rr], rsl);
            }
        }
    } else {
        #pragma unroll
        for (int nt = 0; nt < 4; nt++) {
            const int c = c0 + nt * 8;
            float sx = 1.f, sy = 1.f;
            if (RSCALE) {
                sx = __fdividef(1.f, rsum[(long)bz * H_ + c]);
                sy = __fdividef(1.f, rsum[(long)bz * H_ + c + 1]);
            }
            #pragma unroll
            for (int mt = 0; mt < 4; mt++) {
                const float* a4 = acc[mt][nt];
                #pragma unroll
                for (int h = 0; h < 2; h++) {
                    const int rr = r0 + mt * 16 + h * 8;
                    const float bi = bias ? bias[rr] : 0.f;
                    float vx = fmaf(a4[h * 2 + 0], alpha, bi) * sx;
                    float vy = fmaf(a4[h * 2 + 1], alpha, bi) * sy;
                    const long off = (long)rr * ldc + c;
                    if (resid) {
                        const float2 rv = *reinterpret_cast<const float2*>(&resid[(long)bz * sR + off]);
                        vx += rv.x; vy += rv.y;
                    }
                    store2(&C[off], vx, vy);
                }
            }
        }
    }
}

// ---------------------------------------------------------------------------
extern "C" void kernel_launch(void* const* d_in, const int* in_sizes, int n_in,
                              void* d_out, int out_size)
{
    const float* x     = (const float*)d_in[0];
    const float* gamma = (const float*)d_in[1];
    const float* beta  = (const float*)d_in[2];
    const float* wq    = (const float*)d_in[3];
    const float* bq    = (const float*)d_in[4];
    const float* wk    = (const float*)d_in[5];
    const float* bk    = (const float*)d_in[6];
    const float* wv    = (const float*)d_in[7];
    const float* bv    = (const float*)d_in[8];
    const float* wp    = (const float*)d_in[9];
    const float* bp    = (const float*)d_in[10];
    float* out = (float*)d_out;

    __half *hn, *q, *k, *v, *s, *w;
    float* rsum;
    cudaGetSymbolAddress((void**)&hn, g_hn);
    cudaGetSymbolAddress((void**)&q,  g_q);
    cudaGetSymbolAddress((void**)&k,  g_k);
    cudaGetSymbolAddress((void**)&v,  g_v);
    cudaGetSymbolAddress((void**)&s,  g_s);
    cudaGetSymbolAddress((void**)&w,  g_w);
    cudaGetSymbolAddress((void**)&rsum, g_rsum);

    const long HH = (long)H_ * H_;
    const long CC = (long)C_ * C_;
    const float scale = 0.044194173824159216f;            // 1/sqrt(512)
    const float scale2 = scale * 1.4426950408889634f;     // * log2(e)

    cudaFuncSetAttribute((const void*)hgemm_kernel<false, false, __half, false, false>, cudaFuncAttributeMaxDynamicSharedMemorySize, GEMM_SMEM);
    cudaFuncSetAttribute((const void*)hgemm_kernel<false, false, float,  false, false>, cudaFuncAttributeMaxDynamicSharedMemorySize, GEMM_SMEM);
    cudaFuncSetAttribute((const void*)hgemm_kernel<true,  false, __half, true,  false>, cudaFuncAttributeMaxDynamicSharedMemorySize, GEMM_SMEM);
    cudaFuncSetAttribute((const void*)hgemm_kernel<false, true,  __half, false, true >, cudaFuncAttributeMaxDynamicSharedMemorySize, GEMM_SMEM);

    // 0. weights -> fp16 (+ zero rsum) ; 1. GroupNorm -> fp16
    w2h_kernel<<<1024, 256>>>(wq, wk, wv, wp, w);
    gn_kernel<<<B_ * G_, 256>>>(x, gamma, beta, hn);

    // 2-4. q/k/v = W @ hn_b + bias   (A=[m,k], B=[k,n])
    dim3 gqkv(H_ / BN, C_ / BM, B_);
    hgemm_kernel<false, false, __half, false, false><<<gqkv, 256, GEMM_SMEM>>>(
        w + 0*CC, hn, q, C_, C_, H_, H_, 0, CH, CH, bq, 1.f, nullptr, 0, nullptr);
    hgemm_kernel<false, false, __half, false, false><<<gqkv, 256, GEMM_SMEM>>>(
        w + 1*CC, hn, k, C_, C_, H_, H_, 0, CH, CH, bk, 1.f, nullptr, 0, nullptr);
    hgemm_kernel<false, false, __half, false, false><<<gqkv, 256, GEMM_SMEM>>>(
        w + 2*CC, hn, v, C_, C_, H_, H_, 0, CH, CH, bv, 1.f, nullptr, 0, nullptr);

    // 5. P[b,i,j] = exp(scale * sum_c q[b,c,i] k[b,c,j] - 8), rowsum -> rsum
    dim3 gsc(H_ / BN, H_ / BM, B_);
    hgemm_kernel<true, false, __half, true, false><<<gsc, 256, GEMM_SMEM>>>(
        q, k, s, C_, H_, H_, H_, CH, CH, HH, nullptr, scale2, nullptr, 0, rsum);

    // 6. h_[b,c,i] = (1/rsum[i]) * sum_j v[b,c,j] P[i,j]   (A=[m,k], B=[n,k])
    dim3 gav(H_ / BN, C_ / BM, B_);
    hgemm_kernel<false, true, __half, false, true><<<gav, 256, GEMM_SMEM>>>(
        v, s, hn, H_, H_, H_, H_, CH, HH, CH, nullptr, 1.f, nullptr, 0, rsum);

    // 7. out = x + Wp @ h_ + bp  (fp32 out, residual)
    hgemm_kernel<false, false, float, false, false><<<gqkv, 256, GEMM_SMEM>>>(
        w + 3*CC, hn, out, C_, C_, H_, H_, 0, CH, CH, bp, 1.f, x, CH, nullptr);
}

// round 13
// speedup vs baseline: 1.1185x; 1.1093x over previous
#include <cuda_runtime.h>
#include <cuda_fp16.h>
#include <math.h>
#include <stdint.h>

#define B_ 8
#define C_ 512
#define H_ 2048
#define G_ 32
#define CPG 16
static const long CH = (long)C_ * H_;

// Scratch (device globals: allocation-free contract). All fp16 intermediates.
__device__ __half g_hn[B_*C_*H_];        // GN output; later reused for attn*V output
__device__ __half g_q [B_*C_*H_];
__device__ __half g_k [B_*C_*H_];
__device__ __half g_v [B_*C_*H_];
__device__ __half g_s [(long)B_*H_*H_]; // attention exp-scores (64 MB fp16)
__device__ __half g_w [4*C_*C_];        // fp16 weights: wq,wk,wv,wp
__device__ float  g_rsum[B_*H_];        // softmax row sums (of exp(x-8))

__device__ __forceinline__ uint32_t smem_u32(const void* p) {
    return (uint32_t)__cvta_generic_to_shared(p);
}
__device__ __forceinline__ void st_h4(__half* dst, float4 v) {
    __half2 lo = __floats2half2_rn(v.x, v.y);
    __half2 hi = __floats2half2_rn(v.z, v.w);
    uint2 u;
    u.x = *reinterpret_cast<uint32_t*>(&lo);
    u.y = *reinterpret_cast<uint32_t*>(&hi);
    *reinterpret_cast<uint2*>(dst) = u;
}

// ---------------------------------------------------------------------------
// Weight fp32 -> fp16 conversion (4 x 512 x 512) + zero rsum
// ---------------------------------------------------------------------------
__global__ __launch_bounds__(256) void w2h_kernel(const float* __restrict__ wq,
                                                  const float* __restrict__ wk,
                                                  const float* __restrict__ wv,
                                                  const float* __restrict__ wp,
                                                  __half* __restrict__ dst)
{
    const int gid = blockIdx.x * 256 + threadIdx.x;
    if (gid < B_ * H_) g_rsum[gid] = 0.f;
    const int mat = gid >> 16;
    const int off = (gid & 65535) * 4;
    const float* src = (mat == 0) ? wq : (mat == 1) ? wk : (mat == 2) ? wv : wp;
    float4 v = *reinterpret_cast<const float4*>(src + off);
    st_h4(&dst[(long)mat * C_ * C_ + off], v);
}

// ---------------------------------------------------------------------------
// GroupNorm -> fp16 output
// ---------------------------------------------------------------------------
__global__ __launch_bounds__(256) void gn_kernel(const float* __restrict__ x,
                                                 const float* __restrict__ gamma,
                                                 const float* __restrict__ beta,
                                                 __half* __restrict__ hn)
{
    const int b = blockIdx.x >> 5;
    const int g = blockIdx.x & 31;
    const long base = ((long)b * C_ + (long)g * CPG) * H_;
    const float4* xp = reinterpret_cast<const float4*>(x + base);
    const int NE4 = CPG * H_ / 4;
    const int tid = threadIdx.x;

    float s = 0.f, ss = 0.f;
    for (int i = tid; i < NE4; i += 256) {
        float4 v = xp[i];
        s  += v.x + v.y + v.z + v.w;
        ss += v.x*v.x + v.y*v.y + v.z*v.z + v.w*v.w;
    }
    __shared__ float rs[8], rss[8];
    #pragma unroll
    for (int o = 16; o > 0; o >>= 1) {
        s  += __shfl_down_sync(0xFFFFFFFFu, s,  o);
        ss += __shfl_down_sync(0xFFFFFFFFu, ss, o);
    }
    if ((tid & 31) == 0) { rs[tid >> 5] = s; rss[tid >> 5] = ss; }
    __syncthreads();
    if (tid < 32) {
        s  = (tid < 8) ? rs[tid]  : 0.f;
        ss = (tid < 8) ? rss[tid] : 0.f;
        #pragma unroll
        for (int o = 4; o > 0; o >>= 1) {
            s  += __shfl_down_sync(0xFFFFFFFFu, s,  o);
            ss += __shfl_down_sync(0xFFFFFFFFu, ss, o);
        }
        if (tid == 0) { rs[0] = s; rss[0] = ss; }
    }
    __syncthreads();
    const float mean = rs[0] * (1.f / (CPG * H_));
    const float var  = rss[0] * (1.f / (CPG * H_)) - mean * mean;
    const float inv  = rsqrtf(var + 1e-6f);

    for (int i = tid; i < NE4; i += 256) {
        const int c = g * CPG + (i * 4) / H_;
        const float gm = gamma[c] * inv;
        const float bt = beta[c] - mean * gm;
        float4 v = xp[i];
        float4 o;
        o.x = v.x * gm + bt; o.y = v.y * gm + bt;
        o.z = v.z * gm + bt; o.w = v.w * gm + bt;
        st_h4(&hn[base + (long)i * 4], o);
    }
}

// ---------------------------------------------------------------------------
// Tensor-core fp16 GEMM, XOR-swizzled smem, BK=64, 3 stages,
// ks-level fragment double-buffering. __launch_bounds__(256,2) pins <=128 regs.
//   C[m,n] = alpha * sum_k A(m,k)*B(k,n) (+bias[m]) (+resid fp32)
//   EXPSUM: out = exp2(alpha*acc - 8*log2e)  [alpha pre-scaled by log2e],
//           atomic row-sum into rsum[bz*H+m]
//   RSCALE: out *= 1/rsum[bz*H + n]
// ---------------------------------------------------------------------------
#define BM 128
#define BN 128
#define BK 64
#define NSTAGE 3
#define STG_BYTES 32768
#define GEMM_SMEM (NSTAGE * STG_BYTES)

__device__ __forceinline__ void cp16(uint32_t s, const void* g) {
    asm volatile("cp.async.cg.shared.global [%0], [%1], 16;" :: "r"(s), "l"(g));
}
__device__ __forceinline__ void cp_commit() { asm volatile("cp.async.commit_group;"); }
__device__ __forceinline__ void cp_wait1() { asm volatile("cp.async.wait_group 1;"); }
__device__ __forceinline__ void cp_wait0() { asm volatile("cp.async.wait_group 0;"); }

__device__ __forceinline__ void ldsm4(uint32_t* r, uint32_t a) {
    asm volatile("ldmatrix.sync.aligned.m8n8.x4.shared.b16 {%0,%1,%2,%3}, [%4];"
                 : "=r"(r[0]), "=r"(r[1]), "=r"(r[2]), "=r"(r[3]) : "r"(a));
}
__device__ __forceinline__ void ldsm4t(uint32_t* r, uint32_t a) {
    asm volatile("ldmatrix.sync.aligned.m8n8.x4.trans.shared.b16 {%0,%1,%2,%3}, [%4];"
                 : "=r"(r[0]), "=r"(r[1]), "=r"(r[2]), "=r"(r[3]) : "r"(a));
}
__device__ __forceinline__ void mma16816(float* c, const uint32_t* a, const uint32_t* b) {
    asm volatile("mma.sync.aligned.m16n8k16.row.col.f32.f16.f16.f32 "
                 "{%0,%1,%2,%3}, {%4,%5,%6,%7}, {%8,%9}, {%0,%1,%2,%3};"
                 : "+f"(c[0]), "+f"(c[1]), "+f"(c[2]), "+f"(c[3])
                 : "r"(a[0]), "r"(a[1]), "r"(a[2]), "r"(a[3]), "r"(b[0]), "r"(b[1]));
}
__device__ __forceinline__ void store2(float* p, float x, float y) {
    *reinterpret_cast<float2*>(p) = make_float2(x, y);
}
__device__ __forceinline__ void store2(__half* p, float x, float y) {
    *reinterpret_cast<__half2*>(p) = __floats2half2_rn(x, y);
}

template<bool TA, bool TB, typename OutT, bool EXPSUM, bool RSCALE>
__global__ __launch_bounds__(256, 2) void hgemm_kernel(
    const __half* __restrict__ Ab, const __half* __restrict__ Bb, OutT* __restrict__ Cb,
    int K, int lda, int ldb, int ldc,
    long sA, long sB, long sC,
    const float* __restrict__ bias, float alpha,
    const float* __restrict__ resid, long sR,
    float* __restrict__ rsum)
{
    extern __shared__ __align__(128) char sm[];
    const uint32_t smb = smem_u32(sm);

    const int tid = threadIdx.x;
    const int bz = blockIdx.z;
    const __half* A = Ab + (long)bz * sA;
    const __half* B = Bb + (long)bz * sB;
    OutT* C = Cb + (long)bz * sC;
    const int m0 = blockIdx.y * BM;
    const int n0 = blockIdx.x * BN;

    const int wid = tid >> 5, lane = tid & 31;
    const int wm = (wid & 1) * 64;
    const int wn = (wid >> 1) * 32;

    float acc[4][4][4] = {};

    auto stage = [&](int k0, int buf) {
        const uint32_t ab = smb + buf * STG_BYTES;
        const uint32_t bb = ab + 16384;
        #pragma unroll
        for (int i = 0; i < 4; i++) {
            const int c = tid + i * 256;
            if (!TA) {
                const int row = c >> 3, ch = c & 7;
                const int sw = ch ^ (row & 7);
                cp16(ab + row * 128 + sw * 16,
                     &A[(long)(m0 + row) * lda + k0 + ch * 8]);
            } else {
                const int row = c >> 4, ch = c & 15;
                const int sw = (ch & 8) | ((ch ^ row) & 7);
                cp16(ab + row * 256 + sw * 16,
                     &A[(long)(k0 + row) * lda + m0 + ch * 8]);
            }
        }
        #pragma unroll
        for (int i = 0; i < 4; i++) {
            const int c = tid + i * 256;
            if (!TB) {
                const int row = c >> 4, ch = c & 15;
                const int sw = (ch & 8) | ((ch ^ row) & 7);
                cp16(bb + row * 256 + sw * 16,
                     &B[(long)(k0 + row) * ldb + n0 + ch * 8]);
            } else {
                const int row = c >> 3, ch = c & 7;
                const int sw = ch ^ (row & 7);
                cp16(bb + row * 128 + sw * 16,
                     &B[(long)(n0 + row) * ldb + k0 + ch * 8]);
            }
        }
        cp_commit();
    };

    // fragment loader for one ks step (16 wide)
    auto load_frags = [&](int ks, uint32_t a[4][4], uint32_t b[4][2],
                          uint32_t ab, uint32_t bb) {
        #pragma unroll
        for (int mt = 0; mt < 4; mt++) {
            if (!TA) {
                const int row = wm + mt * 16 + (lane & 15);
                const int ch = (ks >> 3) + (lane >> 4);
                const int sw = ch ^ (row & 7);
                ldsm4(a[mt], ab + row * 128 + sw * 16);
            } else {
                const int kk = ks + (lane >> 4) * 8 + (lane & 7);
                const int mm = wm + mt * 16 + ((lane >> 3) & 1) * 8;
                const int ch = mm >> 3;
                const int sw = (ch & 8) | ((ch ^ kk) & 7);
                ldsm4t(a[mt], ab + kk * 256 + sw * 16);
            }
        }
        #pragma unroll
        for (int nt2 = 0; nt2 < 2; nt2++) {
            uint32_t r[4];
            if (!TB) {
                const int kk = ks + ((lane >> 3) & 1) * 8 + (lane & 7);
                const int ncol = wn + nt2 * 16 + ((lane >> 4) & 1) * 8;
                const int ch = ncol >> 3;
                const int sw = (ch & 8) | ((ch ^ kk) & 7);
                ldsm4t(r, bb + kk * 256 + sw * 16);
            } else {
                const int nn = wn + nt2 * 16 + ((lane >> 4) & 1) * 8 + (lane & 7);
                const int ch = (ks >> 3) + ((lane >> 3) & 1);
                const int sw = ch ^ (nn & 7);
                ldsm4(r, bb + nn * 128 + sw * 16);
            }
            b[2*nt2][0] = r[0]; b[2*nt2][1] = r[1];
            b[2*nt2+1][0] = r[2]; b[2*nt2+1][1] = r[3];
        }
    };

    stage(0, 0);
    stage(BK, 1);

    const int T = K / BK;
    for (int t = 0; t < T; t++) {
        cp_wait1();
        __syncthreads();
        if (t + 2 < T) stage((t + 2) * BK, (t + 2) % NSTAGE);

        const uint32_t ab = smb + (t % NSTAGE) * STG_BYTES;
        const uint32_t bb = ab + 16384;

        uint32_t fa[2][4][4], fb[2][4][2];
        load_frags(0, fa[0], fb[0], ab, bb);
        #pragma unroll
        for (int s4 = 0; s4 < 4; s4++) {
            const int cur = s4 & 1, nxt = cur ^ 1;
            if (s4 < 3) load_frags((s4 + 1) * 16, fa[nxt], fb[nxt], ab, bb);
            #pragma unroll
            for (int mt = 0; mt < 4; mt++)
                #pragma unroll
                for (int nt = 0; nt < 4; nt++)
                    mma16816(acc[mt][nt], fa[cur][mt], fb[cur][nt]);
        }
    }
    cp_wait0();

    // ---- epilogue ----
    const int r0 = m0 + wm + (lane >> 2);
    const int c0 = n0 + wn + (lane & 3) * 2;
    if (EXPSUM) {
        // alpha is pre-scaled by log2(e); exp(x-8) = exp2(x*log2e - 8*log2e)
        #pragma unroll
        for (int mt = 0; mt < 4; mt++) {
            #pragma unroll
            for (int h = 0; h < 2; h++) {
                const int rr = r0 + mt * 16 + h * 8;
                float rsl = 0.f;
                #pragma unroll
                for (int nt = 0; nt < 4; nt++) {
                    const float* a4 = acc[mt][nt];
                    float vx = exp2f(fmaf(a4[h*2+0], alpha, -11.541560327111708f));
                    float vy = exp2f(fmaf(a4[h*2+1], alpha, -11.541560327111708f));
                    store2(&C[(long)rr * ldc + c0 + nt * 8], vx, vy);
                    rsl += vx + vy;
                }
                rsl += __shfl_xor_sync(0xFFFFFFFFu, rsl, 1);
                rsl += __shfl_xor_sync(0xFFFFFFFFu, rsl, 2);
                if ((lane & 3) == 0)
                    atomicAdd(&rsum[(long)bz * H_ + rr], rsl);
            }
        }
    } else {
        #pragma unroll
        for (int mt = 0; mt < 4; mt++) {
            #pragma unroll
            for (int nt = 0; nt < 4; nt++) {
                const float* a4 = acc[mt][nt];
                const int c = c0 + nt * 8;
                float sx = 1.f, sy = 1.f;
                if (RSCALE) {
                    sx = __fdividef(1.f, rsum[(long)bz * H_ + c]);
                    sy = __fdividef(1.f, rsum[(long)bz * H_ + c + 1]);
                }
                #pragma unroll
                for (int h = 0; h < 2; h++) {
                    const int rr = r0 + mt * 16 + h * 8;
                    const float bi = bias ? bias[rr] : 0.f;
                    float vx = fmaf(a4[h * 2 + 0], alpha, bi) * sx;
                    float vy = fmaf(a4[h * 2 + 1], alpha, bi) * sy;
                    const long off = (long)rr * ldc + c;
                    if (resid) {
                        const float2 rv = *reinterpret_cast<const float2*>(&resid[(long)bz * sR + off]);
                        vx += rv.x; vy += rv.y;
                    }
                    store2(&C[off], vx, vy);
                }
            }
        }
    }
}

// ---------------------------------------------------------------------------
extern "C" void kernel_launch(void* const* d_in, const int* in_sizes, int n_in,
                              void* d_out, int out_size)
{
    const float* x     = (const float*)d_in[0];
    const float* gamma = (const float*)d_in[1];
    const float* beta  = (const float*)d_in[2];
    const float* wq    = (const float*)d_in[3];
    const float* bq    = (const float*)d_in[4];
    const float* wk    = (const float*)d_in[5];
    const float* bk    = (const float*)d_in[6];
    const float* wv    = (const float*)d_in[7];
    const float* bv    = (const float*)d_in[8];
    const float* wp    = (const float*)d_in[9];
    const float* bp    = (const float*)d_in[10];
    float* out = (float*)d_out;

    __half *hn, *q, *k, *v, *s, *w;
    float* rsum;
    cudaGetSymbolAddress((void**)&hn, g_hn);
    cudaGetSymbolAddress((void**)&q,  g_q);
    cudaGetSymbolAddress((void**)&k,  g_k);
    cudaGetSymbolAddress((void**)&v,  g_v);
    cudaGetSymbolAddress((void**)&s,  g_s);
    cudaGetSymbolAddress((void**)&w,  g_w);
    cudaGetSymbolAddress((void**)&rsum, g_rsum);

    const long HH = (long)H_ * H_;
    const long CC = (long)C_ * C_;
    const float scale = 0.044194173824159216f;            // 1/sqrt(512)
    const float scale2 = scale * 1.4426950408889634f;     // * log2(e)

    cudaFuncSetAttribute((const void*)hgemm_kernel<false, false, __half, false, false>, cudaFuncAttributeMaxDynamicSharedMemorySize, GEMM_SMEM);
    cudaFuncSetAttribute((const void*)hgemm_kernel<false, false, float,  false, false>, cudaFuncAttributeMaxDynamicSharedMemorySize, GEMM_SMEM);
    cudaFuncSetAttribute((const void*)hgemm_kernel<true,  false, __half, true,  false>, cudaFuncAttributeMaxDynamicSharedMemorySize, GEMM_SMEM);
    cudaFuncSetAttribute((const void*)hgemm_kernel<false, true,  __half, false, true >, cudaFuncAttributeMaxDynamicSharedMemorySize, GEMM_SMEM);

    // 0. weights -> fp16 (+ zero rsum) ; 1. GroupNorm -> fp16
    w2h_kernel<<<1024, 256>>>(wq, wk, wv, wp, w);
    gn_kernel<<<B_ * G_, 256>>>(x, gamma, beta, hn);

    // 2-4. q/k/v = W @ hn_b + bias   (A=[m,k], B=[k,n])
    dim3 gqkv(H_ / BN, C_ / BM, B_);
    hgemm_kernel<false, false, __half, false, false><<<gqkv, 256, GEMM_SMEM>>>(
        w + 0*CC, hn, q, C_, C_, H_, H_, 0, CH, CH, bq, 1.f, nullptr, 0, nullptr);
    hgemm_kernel<false, false, __half, false, false><<<gqkv, 256, GEMM_SMEM>>>(
        w + 1*CC, hn, k, C_, C_, H_, H_, 0, CH, CH, bk, 1.f, nullptr, 0, nullptr);
    hgemm_kernel<false, false, __half, false, false><<<gqkv, 256, GEMM_SMEM>>>(
        w + 2*CC, hn, v, C_, C_, H_, H_, 0, CH, CH, bv, 1.f, nullptr, 0, nullptr);

    // 5. P[b,i,j] = exp(scale * sum_c q[b,c,i] k[b,c,j] - 8), rowsum -> rsum
    dim3 gsc(H_ / BN, H_ / BM, B_);
    hgemm_kernel<true, false, __half, true, false><<<gsc, 256, GEMM_SMEM>>>(
        q, k, s, C_, H_, H_, H_, CH, CH, HH, nullptr, scale2, nullptr, 0, rsum);

    // 6. h_[b,c,i] = (1/rsum[i]) * sum_j v[b,c,j] P[i,j]   (A=[m,k], B=[n,k])
    dim3 gav(H_ / BN, C_ / BM, B_);
    hgemm_kernel<false, true, __half, false, true><<<gav, 256, GEMM_SMEM>>>(
        v, s, hn, H_, H_, H_, H_, CH, HH, CH, nullptr, 1.f, nullptr, 0, rsum);

    // 7. out = x + Wp @ h_ + bp  (fp32 out, residual)
    hgemm_kernel<false, false, float, false, false><<<gqkv, 256, GEMM_SMEM>>>(
        w + 3*CC, hn, out, C_, C_, H_, H_, 0, CH, CH, bp, 1.f, x, CH, nullptr);
}

// round 15
// speedup vs baseline: 1.1562x; 1.0337x over previous
#include <cuda_runtime.h>
#include <cuda_fp16.h>
#include <math.h>
#include <stdint.h>

#define B_ 8
#define C_ 512
#define H_ 2048
#define G_ 32
#define CPG 16
static const long CH = (long)C_ * H_;

// Scratch (device globals: allocation-free contract). All fp16 intermediates.
__device__ __half g_hn [B_*C_*H_];        // GN output; later reused for attn*V output
__device__ __half g_qkv[3L*B_*C_*H_];     // [mat][b][C][H], mat: 0=q 1=k 2=v
__device__ __half g_s  [(long)B_*H_*H_];  // attention exp-scores (64 MB fp16)
__device__ __half g_w  [3*C_*C_];         // fp16 weights: wq,wk,wv stacked
__device__ __half g_wp [C_*C_];           // fp16 proj weight
__device__ float  g_bias[3*C_];           // concat q/k/v bias
__device__ float  g_rsum[B_*H_];          // softmax row sums (of exp(x-8))

__device__ __forceinline__ uint32_t smem_u32(const void* p) {
    return (uint32_t)__cvta_generic_to_shared(p);
}
__device__ __forceinline__ void st_h4(__half* dst, float4 v) {
    __half2 lo = __floats2half2_rn(v.x, v.y);
    __half2 hi = __floats2half2_rn(v.z, v.w);
    uint2 u;
    u.x = *reinterpret_cast<uint32_t*>(&lo);
    u.y = *reinterpret_cast<uint32_t*>(&hi);
    *reinterpret_cast<uint2*>(dst) = u;
}

// ---------------------------------------------------------------------------
// Weight fp32 -> fp16 (wq|wk|wv stacked, wp separate) + bias concat + rsum zero
// ---------------------------------------------------------------------------
__global__ __launch_bounds__(256) void w2h_kernel(const float* __restrict__ wq,
                                                  const float* __restrict__ wk,
                                                  const float* __restrict__ wv,
                                                  const float* __restrict__ wp,
                                                  const float* __restrict__ bq,
                                                  const float* __restrict__ bk,
                                                  const float* __restrict__ bv)
{
    const int gid = blockIdx.x * 256 + threadIdx.x;
    if (gid < B_ * H_) g_rsum[gid] = 0.f;
    if (gid < 3 * C_) {
        const float* b = (gid < C_) ? bq : (gid < 2*C_) ? bk : bv;
        g_bias[gid] = b[gid & (C_ - 1)];
    }
    const int mat = gid >> 16;
    const int off = (gid & 65535) * 4;
    if (mat < 3) {
        const float* src = (mat == 0) ? wq : (mat == 1) ? wk : wv;
        float4 v = *reinterpret_cast<const float4*>(src + off);
        st_h4(&g_w[(long)mat * C_ * C_ + off], v);
    } else {
        float4 v = *reinterpret_cast<const float4*>(wp + off);
        st_h4(&g_wp[off], v);
    }
}

// ---------------------------------------------------------------------------
// GroupNorm -> fp16 output
// ---------------------------------------------------------------------------
__global__ __launch_bounds__(256) void gn_kernel(const float* __restrict__ x,
                                                 const float* __restrict__ gamma,
                                                 const float* __restrict__ beta,
                                                 __half* __restrict__ hn)
{
    const int b = blockIdx.x >> 5;
    const int g = blockIdx.x & 31;
    const long base = ((long)b * C_ + (long)g * CPG) * H_;
    const float4* xp = reinterpret_cast<const float4*>(x + base);
    const int NE4 = CPG * H_ / 4;
    const int tid = threadIdx.x;

    float s = 0.f, ss = 0.f;
    for (int i = tid; i < NE4; i += 256) {
        float4 v = xp[i];
        s  += v.x + v.y + v.z + v.w;
        ss += v.x*v.x + v.y*v.y + v.z*v.z + v.w*v.w;
    }
    __shared__ float rs[8], rss[8];
    #pragma unroll
    for (int o = 16; o > 0; o >>= 1) {
        s  += __shfl_down_sync(0xFFFFFFFFu, s,  o);
        ss += __shfl_down_sync(0xFFFFFFFFu, ss, o);
    }
    if ((tid & 31) == 0) { rs[tid >> 5] = s; rss[tid >> 5] = ss; }
    __syncthreads();
    if (tid < 32) {
        s  = (tid < 8) ? rs[tid]  : 0.f;
        ss = (tid < 8) ? rss[tid] : 0.f;
        #pragma unroll
        for (int o = 4; o > 0; o >>= 1) {
            s  += __shfl_down_sync(0xFFFFFFFFu, s,  o);
            ss += __shfl_down_sync(0xFFFFFFFFu, ss, o);
        }
        if (tid == 0) { rs[0] = s; rss[0] = ss; }
    }
    __syncthreads();
    const float mean = rs[0] * (1.f / (CPG * H_));
    const float var  = rss[0] * (1.f / (CPG * H_)) - mean * mean;
    const float inv  = rsqrtf(var + 1e-6f);

    for (int i = tid; i < NE4; i += 256) {
        const int c = g * CPG + (i * 4) / H_;
        const float gm = gamma[c] * inv;
        const float bt = beta[c] - mean * gm;
        float4 v = xp[i];
        float4 o;
        o.x = v.x * gm + bt; o.y = v.y * gm + bt;
        o.z = v.z * gm + bt; o.w = v.w * gm + bt;
        st_h4(&hn[base + (long)i * 4], o);
    }
}

// ---------------------------------------------------------------------------
// Tensor-core fp16 GEMM, XOR-swizzled smem, BK=64, 3 stages,
// ks-level fragment double-buffering. __launch_bounds__(256,2) pins <=128 regs.
//   C[m,n] = alpha * sum_k A(m,k)*B(k,n) (+bias[m]) (+resid fp32)
//   EXPSUM: out = exp2(alpha*acc - 8*log2e)  [alpha pre-scaled by log2e],
//           atomic row-sum into rsum[bz*H+m]
//   RSCALE: out *= 1/rsum[bz*H + n]
//   QKV3:   blockIdx.z encodes mat*8+b; A += mat*sA, B += b*sB, C += z*sC,
//           bias += mat*C_
// ---------------------------------------------------------------------------
#define BM 128
#define BN 128
#define BK 64
#define NSTAGE 3
#define STG_BYTES 32768
#define GEMM_SMEM (NSTAGE * STG_BYTES)

__device__ __forceinline__ void cp16(uint32_t s, const void* g) {
    asm volatile("cp.async.cg.shared.global [%0], [%1], 16;" :: "r"(s), "l"(g));
}
__device__ __forceinline__ void cp_commit() { asm volatile("cp.async.commit_group;"); }
__device__ __forceinline__ void cp_wait1() { asm volatile("cp.async.wait_group 1;"); }
__device__ __forceinline__ void cp_wait0() { asm volatile("cp.async.wait_group 0;"); }

__device__ __forceinline__ void ldsm4(uint32_t* r, uint32_t a) {
    asm volatile("ldmatrix.sync.aligned.m8n8.x4.shared.b16 {%0,%1,%2,%3}, [%4];"
                 : "=r"(r[0]), "=r"(r[1]), "=r"(r[2]), "=r"(r[3]) : "r"(a));
}
__device__ __forceinline__ void ldsm4t(uint32_t* r, uint32_t a) {
    asm volatile("ldmatrix.sync.aligned.m8n8.x4.trans.shared.b16 {%0,%1,%2,%3}, [%4];"
                 : "=r"(r[0]), "=r"(r[1]), "=r"(r[2]), "=r"(r[3]) : "r"(a));
}
__device__ __forceinline__ void mma16816(float* c, const uint32_t* a, const uint32_t* b) {
    asm volatile("mma.sync.aligned.m16n8k16.row.col.f32.f16.f16.f32 "
                 "{%0,%1,%2,%3}, {%4,%5,%6,%7}, {%8,%9}, {%0,%1,%2,%3};"
                 : "+f"(c[0]), "+f"(c[1]), "+f"(c[2]), "+f"(c[3])
                 : "r"(a[0]), "r"(a[1]), "r"(a[2]), "r"(a[3]), "r"(b[0]), "r"(b[1]));
}
__device__ __forceinline__ void store2(float* p, float x, float y) {
    *reinterpret_cast<float2*>(p) = make_float2(x, y);
}
__device__ __forceinline__ void store2(__half* p, float x, float y) {
    *reinterpret_cast<__half2*>(p) = __floats2half2_rn(x, y);
}

template<bool TA, bool TB, typename OutT, bool EXPSUM, bool RSCALE, bool QKV3>
__global__ __launch_bounds__(256, 2) void hgemm_kernel(
    const __half* __restrict__ Ab, const __half* __restrict__ Bb, OutT* __restrict__ Cb,
    int K, int lda, int ldb, int ldc,
    long sA, long sB, long sC,
    const float* __restrict__ bias, float alpha,
    const float* __restrict__ resid, long sR,
    float* __restrict__ rsum)
{
    extern __shared__ __align__(128) char sm[];
    const uint32_t smb = smem_u32(sm);

    const int tid = threadIdx.x;
    const int bz = blockIdx.z;
    const __half* A;
    const __half* B;
    OutT* C;
    const float* biasp = bias;
    if (QKV3) {
        const int mat = bz >> 3;
        const int b   = bz & 7;
        A = Ab + (long)mat * sA;
        B = Bb + (long)b * sB;
        C = Cb + (long)bz * sC;
        biasp = bias + mat * C_;
    } else {
        A = Ab + (long)bz * sA;
        B = Bb + (long)bz * sB;
        C = Cb + (long)bz * sC;
    }
    const int m0 = blockIdx.y * BM;
    const int n0 = blockIdx.x * BN;

    const int wid = tid >> 5, lane = tid & 31;
    const int wm = (wid & 1) * 64;
    const int wn = (wid >> 1) * 32;

    float acc[4][4][4] = {};

    auto stage = [&](int k0, int buf) {
        const uint32_t ab = smb + buf * STG_BYTES;
        const uint32_t bb = ab + 16384;
        #pragma unroll
        for (int i = 0; i < 4; i++) {
            const int c = tid + i * 256;
            if (!TA) {
                const int row = c >> 3, ch = c & 7;
                const int sw = ch ^ (row & 7);
                cp16(ab + row * 128 + sw * 16,
                     &A[(long)(m0 + row) * lda + k0 + ch * 8]);
            } else {
                const int row = c >> 4, ch = c & 15;
                const int sw = (ch & 8) | ((ch ^ row) & 7);
                cp16(ab + row * 256 + sw * 16,
                     &A[(long)(k0 + row) * lda + m0 + ch * 8]);
            }
        }
        #pragma unroll
        for (int i = 0; i < 4; i++) {
            const int c = tid + i * 256;
            if (!TB) {
                const int row = c >> 4, ch = c & 15;
                const int sw = (ch & 8) | ((ch ^ row) & 7);
                cp16(bb + row * 256 + sw * 16,
                     &B[(long)(k0 + row) * ldb + n0 + ch * 8]);
            } else {
                const int row = c >> 3, ch = c & 7;
                const int sw = ch ^ (row & 7);
                cp16(bb + row * 128 + sw * 16,
                     &B[(long)(n0 + row) * ldb + k0 + ch * 8]);
            }
        }
        cp_commit();
    };

    // fragment loader for one ks step (16 wide)
    auto load_frags = [&](int ks, uint32_t a[4][4], uint32_t b[4][2],
                          uint32_t ab, uint32_t bb) {
        #pragma unroll
        for (int mt = 0; mt < 4; mt++) {
            if (!TA) {
                const int row = wm + mt * 16 + (lane & 15);
                const int ch = (ks >> 3) + (lane >> 4);
                const int sw = ch ^ (row & 7);
                ldsm4(a[mt], ab + row * 128 + sw * 16);
            } else {
                const int kk = ks + (lane >> 4) * 8 + (lane & 7);
                const int mm = wm + mt * 16 + ((lane >> 3) & 1) * 8;
                const int ch = mm >> 3;
                const int sw = (ch & 8) | ((ch ^ kk) & 7);
                ldsm4t(a[mt], ab + kk * 256 + sw * 16);
            }
        }
        #pragma unroll
        for (int nt2 = 0; nt2 < 2; nt2++) {
            uint32_t r[4];
            if (!TB) {
                const int kk = ks + ((lane >> 3) & 1) * 8 + (lane & 7);
                const int ncol = wn + nt2 * 16 + ((lane >> 4) & 1) * 8;
                const int ch = ncol >> 3;
                const int sw = (ch & 8) | ((ch ^ kk) & 7);
                ldsm4t(r, bb + kk * 256 + sw * 16);
            } else {
                const int nn = wn + nt2 * 16 + ((lane >> 4) & 1) * 8 + (lane & 7);
                const int ch = (ks >> 3) + ((lane >> 3) & 1);
                const int sw = ch ^ (nn & 7);
                ldsm4(r, bb + nn * 128 + sw * 16);
            }
            b[2*nt2][0] = r[0]; b[2*nt2][1] = r[1];
            b[2*nt2+1][0] = r[2]; b[2*nt2+1][1] = r[3];
        }
    };

    stage(0, 0);
    stage(BK, 1);

    const int T = K / BK;
    for (int t = 0; t < T; t++) {
        cp_wait1();
        __syncthreads();
        if (t + 2 < T) stage((t + 2) * BK, (t + 2) % NSTAGE);

        const uint32_t ab = smb + (t % NSTAGE) * STG_BYTES;
        const uint32_t bb = ab + 16384;

        uint32_t fa[2][4][4], fb[2][4][2];
        load_frags(0, fa[0], fb[0], ab, bb);
        #pragma unroll
        for (int s4 = 0; s4 < 4; s4++) {
            const int cur = s4 & 1, nxt = cur ^ 1;
            if (s4 < 3) load_frags((s4 + 1) * 16, fa[nxt], fb[nxt], ab, bb);
            #pragma unroll
            for (int mt = 0; mt < 4; mt++)
                #pragma unroll
                for (int nt = 0; nt < 4; nt++)
                    mma16816(acc[mt][nt], fa[cur][mt], fb[cur][nt]);
        }
    }
    cp_wait0();

    // ---- epilogue ----
    const int r0 = m0 + wm + (lane >> 2);
    const int c0 = n0 + wn + (lane & 3) * 2;
    if (EXPSUM) {
        // alpha is pre-scaled by log2(e); exp(x-8) = exp2(x*log2e - 8*log2e)
        #pragma unroll
        for (int mt = 0; mt < 4; mt++) {
            #pragma unroll
            for (int h = 0; h < 2; h++) {
                const int rr = r0 + mt * 16 + h * 8;
                float rsl = 0.f;
                #pragma unroll
                for (int nt = 0; nt < 4; nt++) {
                    const float* a4 = acc[mt][nt];
                    float vx = exp2f(fmaf(a4[h*2+0], alpha, -11.541560327111708f));
                    float vy = exp2f(fmaf(a4[h*2+1], alpha, -11.541560327111708f));
                    store2(&C[(long)rr * ldc + c0 + nt * 8], vx, vy);
                    rsl += vx + vy;
                }
                rsl += __shfl_xor_sync(0xFFFFFFFFu, rsl, 1);
                rsl += __shfl_xor_sync(0xFFFFFFFFu, rsl, 2);
                if ((lane & 3) == 0)
                    atomicAdd(&rsum[(long)bz * H_ + rr], rsl);
            }
        }
    } else {
        #pragma unroll
        for (int mt = 0; mt < 4; mt++) {
            #pragma unroll
            for (int nt = 0; nt < 4; nt++) {
                const float* a4 = acc[mt][nt];
                const int c = c0 + nt * 8;
                float sx = 1.f, sy = 1.f;
                if (RSCALE) {
                    sx = __fdividef(1.f, rsum[(long)bz * H_ + c]);
                    sy = __fdividef(1.f, rsum[(long)bz * H_ + c + 1]);
                }
                #pragma unroll
                for (int h = 0; h < 2; h++) {
                    const int rr = r0 + mt * 16 + h * 8;
                    const float bi = biasp ? biasp[rr] : 0.f;
                    float vx = fmaf(a4[h * 2 + 0], alpha, bi) * sx;
                    float vy = fmaf(a4[h * 2 + 1], alpha, bi) * sy;
                    const long off = (long)rr * ldc + c;
                    if (resid) {
                        const float2 rv = *reinterpret_cast<const float2*>(&resid[(long)bz * sR + off]);
                        vx += rv.x; vy += rv.y;
                    }
                    store2(&C[off], vx, vy);
                }
            }
        }
    }
}

// ---------------------------------------------------------------------------
extern "C" void kernel_launch(void* const* d_in, const int* in_sizes, int n_in,
                              void* d_out, int out_size)
{
    const float* x     = (const float*)d_in[0];
    const float* gamma = (const float*)d_in[1];
    const float* beta  = (const float*)d_in[2];
    const float* wq    = (const float*)d_in[3];
    const float* bq    = (const float*)d_in[4];
    const float* wk    = (const float*)d_in[5];
    const float* bk    = (const float*)d_in[6];
    const float* wv    = (const float*)d_in[7];
    const float* bv    = (const float*)d_in[8];
    const float* wp    = (const float*)d_in[9];
    const float* bp    = (const float*)d_in[10];
    float* out = (float*)d_out;

    __half *hn, *qkv, *s, *w, *wph;
    float *rsum, *biasf;
    cudaGetSymbolAddress((void**)&hn,  g_hn);
    cudaGetSymbolAddress((void**)&qkv, g_qkv);
    cudaGetSymbolAddress((void**)&s,   g_s);
    cudaGetSymbolAddress((void**)&w,   g_w);
    cudaGetSymbolAddress((void**)&wph, g_wp);
    cudaGetSymbolAddress((void**)&rsum, g_rsum);
    cudaGetSymbolAddress((void**)&biasf, g_bias);

    const long HH = (long)H_ * H_;
    const long CC = (long)C_ * C_;
    const float scale = 0.044194173824159216f;            // 1/sqrt(512)
    const float scale2 = scale * 1.4426950408889634f;     // * log2(e)

    cudaFuncSetAttribute((const void*)hgemm_kernel<false, false, __half, false, false, true >, cudaFuncAttributeMaxDynamicSharedMemorySize, GEMM_SMEM);
    cudaFuncSetAttribute((const void*)hgemm_kernel<false, false, float,  false, false, false>, cudaFuncAttributeMaxDynamicSharedMemorySize, GEMM_SMEM);
    cudaFuncSetAttribute((const void*)hgemm_kernel<true,  false, __half, true,  false, false>, cudaFuncAttributeMaxDynamicSharedMemorySize, GEMM_SMEM);
    cudaFuncSetAttribute((const void*)hgemm_kernel<false, true,  __half, false, true,  false>, cudaFuncAttributeMaxDynamicSharedMemorySize, GEMM_SMEM);

    // 0. weights -> fp16 (+ bias concat + zero rsum) ; 1. GroupNorm -> fp16
    w2h_kernel<<<1024, 256>>>(wq, wk, wv, wp, bq, bk, bv);
    gn_kernel<<<B_ * G_, 256>>>(x, gamma, beta, hn);

    // 2. fused q/k/v: grid.z = mat*8+b  -> g_qkv[mat][b][C][H]
    dim3 gqkv(H_ / BN, C_ / BM, 24);
    hgemm_kernel<false, false, __half, false, false, true><<<gqkv, 256, GEMM_SMEM>>>(
        w, hn, qkv, C_, C_, H_, H_, CC, CH, CH, biasf, 1.f, nullptr, 0, nullptr);

    const __half* qp = qkv;                 // mat 0
    const __half* kp = qkv + 8 * CH;        // mat 1
    const __half* vp = qkv + 16 * CH;       // mat 2

    // 3. P[b,i,j] = exp(scale * sum_c q[b,c,i] k[b,c,j] - 8), rowsum -> rsum
    dim3 gsc(H_ / BN, H_ / BM, B_);
    hgemm_kernel<true, false, __half, true, false, false><<<gsc, 256, GEMM_SMEM>>>(
        qp, kp, s, C_, H_, H_, H_, CH, CH, HH, nullptr, scale2, nullptr, 0, rsum);

    // 4. h_[b,c,i] = (1/rsum[i]) * sum_j v[b,c,j] P[i,j]   (A=[m,k], B=[n,k])
    dim3 gav(H_ / BN, C_ / BM, B_);
    hgemm_kernel<false, true, __half, false, true, false><<<gav, 256, GEMM_SMEM>>>(
        vp, s, hn, H_, H_, H_, H_, CH, HH, CH, nullptr, 1.f, nullptr, 0, rsum);

    // 5. out = x + Wp @ h_ + bp  (fp32 out, residual)
    dim3 gpr(H_ / BN, C_ / BM, B_);
    hgemm_kernel<false, false, float, false, false, false><<<gpr, 256, GEMM_SMEM>>>(
        wph, hn, out, C_, C_, H_, H_, 0, CH, CH, bp, 1.f, x, CH, nullptr);
}

// round 17
// speedup vs baseline: 1.1622x; 1.0052x over previous
#include <cuda_runtime.h>
#include <cuda_fp16.h>
#include <math.h>
#include <stdint.h>

#define B_ 8
#define C_ 512
#define H_ 2048
#define G_ 32
#define CPG 16
static const long CH = (long)C_ * H_;

// Scratch (device globals: allocation-free contract). All fp16 intermediates.
__device__ __half g_hn [B_*C_*H_];        // GN output; later reused for attn*V output
__device__ __half g_qkv[3L*B_*C_*H_];     // [mat][b][C][H], mat: 0=q 1=k 2=v
__device__ __half g_s  [(long)B_*H_*H_];  // attention exp-scores (64 MB fp16)
__device__ __half g_w  [3*C_*C_];         // fp16 weights: wq,wk,wv stacked
__device__ __half g_wp [C_*C_];           // fp16 proj weight
__device__ float  g_bias[3*C_];           // concat q/k/v bias
__device__ float  g_rsum[B_*H_];          // softmax row sums (of exp(x-8))

__device__ __forceinline__ uint32_t smem_u32(const void* p) {
    return (uint32_t)__cvta_generic_to_shared(p);
}
__device__ __forceinline__ void st_h4(__half* dst, float4 v) {
    __half2 lo = __floats2half2_rn(v.x, v.y);
    __half2 hi = __floats2half2_rn(v.z, v.w);
    uint2 u;
    u.x = *reinterpret_cast<uint32_t*>(&lo);
    u.y = *reinterpret_cast<uint32_t*>(&hi);
    *reinterpret_cast<uint2*>(dst) = u;
}

// ---------------------------------------------------------------------------
// Fused prep: blocks [0,256) = GroupNorm; blocks [256,1280) = weight fp16
// conversion + bias concat + rsum zero. Independent work, one launch.
// ---------------------------------------------------------------------------
__global__ __launch_bounds__(256) void prep_kernel(const float* __restrict__ x,
                                                   const float* __restrict__ gamma,
                                                   const float* __restrict__ beta,
                                                   __half* __restrict__ hn,
                                                   const float* __restrict__ wq,
                                                   const float* __restrict__ wk,
                                                   const float* __restrict__ wv,
                                                   const float* __restrict__ wp,
                                                   const float* __restrict__ bq,
                                                   const float* __restrict__ bk,
                                                   const float* __restrict__ bv)
{
    const int tid = threadIdx.x;
    if (blockIdx.x >= 256) {
        // ---- weight conversion path ----
        const int gid = (blockIdx.x - 256) * 256 + tid;
        if (gid < B_ * H_) g_rsum[gid] = 0.f;
        if (gid < 3 * C_) {
            const float* b = (gid < C_) ? bq : (gid < 2*C_) ? bk : bv;
            g_bias[gid] = b[gid & (C_ - 1)];
        }
        const int mat = gid >> 16;
        const int off = (gid & 65535) * 4;
        if (mat < 3) {
            const float* src = (mat == 0) ? wq : (mat == 1) ? wk : wv;
            float4 v = *reinterpret_cast<const float4*>(src + off);
            st_h4(&g_w[(long)mat * C_ * C_ + off], v);
        } else {
            float4 v = *reinterpret_cast<const float4*>(wp + off);
            st_h4(&g_wp[off], v);
        }
        return;
    }
    // ---- GroupNorm path ----
    const int b = blockIdx.x >> 5;
    const int g = blockIdx.x & 31;
    const long base = ((long)b * C_ + (long)g * CPG) * H_;
    const float4* xp = reinterpret_cast<const float4*>(x + base);
    const int NE4 = CPG * H_ / 4;

    float s = 0.f, ss = 0.f;
    for (int i = tid; i < NE4; i += 256) {
        float4 v = xp[i];
        s  += v.x + v.y + v.z + v.w;
        ss += v.x*v.x + v.y*v.y + v.z*v.z + v.w*v.w;
    }
    __shared__ float rs[8], rss[8];
    #pragma unroll
    for (int o = 16; o > 0; o >>= 1) {
        s  += __shfl_down_sync(0xFFFFFFFFu, s,  o);
        ss += __shfl_down_sync(0xFFFFFFFFu, ss, o);
    }
    if ((tid & 31) == 0) { rs[tid >> 5] = s; rss[tid >> 5] = ss; }
    __syncthreads();
    if (tid < 32) {
        s  = (tid < 8) ? rs[tid]  : 0.f;
        ss = (tid < 8) ? rss[tid] : 0.f;
        #pragma unroll
        for (int o = 4; o > 0; o >>= 1) {
            s  += __shfl_down_sync(0xFFFFFFFFu, s,  o);
            ss += __shfl_down_sync(0xFFFFFFFFu, ss, o);
        }
        if (tid == 0) { rs[0] = s; rss[0] = ss; }
    }
    __syncthreads();
    const float mean = rs[0] * (1.f / (CPG * H_));
    const float var  = rss[0] * (1.f / (CPG * H_)) - mean * mean;
    const float inv  = rsqrtf(var + 1e-6f);

    for (int i = tid; i < NE4; i += 256) {
        const int c = g * CPG + (i * 4) / H_;
        const float gm = gamma[c] * inv;
        const float bt = beta[c] - mean * gm;
        float4 v = xp[i];
        float4 o;
        o.x = v.x * gm + bt; o.y = v.y * gm + bt;
        o.z = v.z * gm + bt; o.w = v.w * gm + bt;
        st_h4(&hn[base + (long)i * 4], o);
    }
}

// ---------------------------------------------------------------------------
// Tensor-core fp16 GEMM, XOR-swizzled smem, BK=64, 3 stages,
// ks-level fragment double-buffering. __launch_bounds__(256,2) pins <=128 regs.
//   C[m,n] = alpha * sum_k A(m,k)*B(k,n) (+bias[m]) (+resid fp32)
//   EXPSUM: out = exp2(alpha*acc - 8*log2e) via h2exp2 (f16x2 MUFU),
//           atomic row-sum into rsum[bz*H+m]
//   RSCALE: out *= 1/rsum[bz*H + n]
//   QKV3:   blockIdx.z encodes mat*8+b
// ---------------------------------------------------------------------------
#define BM 128
#define BN 128
#define BK 64
#define NSTAGE 3
#define STG_BYTES 32768
#define GEMM_SMEM (NSTAGE * STG_BYTES)

__device__ __forceinline__ void cp16(uint32_t s, const void* g) {
    asm volatile("cp.async.cg.shared.global [%0], [%1], 16;" :: "r"(s), "l"(g));
}
__device__ __forceinline__ void cp_commit() { asm volatile("cp.async.commit_group;"); }
__device__ __forceinline__ void cp_wait1() { asm volatile("cp.async.wait_group 1;"); }
__device__ __forceinline__ void cp_wait0() { asm volatile("cp.async.wait_group 0;"); }

__device__ __forceinline__ void ldsm4(uint32_t* r, uint32_t a) {
    asm volatile("ldmatrix.sync.aligned.m8n8.x4.shared.b16 {%0,%1,%2,%3}, [%4];"
                 : "=r"(r[0]), "=r"(r[1]), "=r"(r[2]), "=r"(r[3]) : "r"(a));
}
__device__ __forceinline__ void ldsm4t(uint32_t* r, uint32_t a) {
    asm volatile("ldmatrix.sync.aligned.m8n8.x4.trans.shared.b16 {%0,%1,%2,%3}, [%4];"
                 : "=r"(r[0]), "=r"(r[1]), "=r"(r[2]), "=r"(r[3]) : "r"(a));
}
__device__ __forceinline__ void mma16816(float* c, const uint32_t* a, const uint32_t* b) {
    asm volatile("mma.sync.aligned.m16n8k16.row.col.f32.f16.f16.f32 "
                 "{%0,%1,%2,%3}, {%4,%5,%6,%7}, {%8,%9}, {%0,%1,%2,%3};"
                 : "+f"(c[0]), "+f"(c[1]), "+f"(c[2]), "+f"(c[3])
                 : "r"(a[0]), "r"(a[1]), "r"(a[2]), "r"(a[3]), "r"(b[0]), "r"(b[1]));
}
__device__ __forceinline__ void store2(float* p, float x, float y) {
    *reinterpret_cast<float2*>(p) = make_float2(x, y);
}
__device__ __forceinline__ void store2(__half* p, float x, float y) {
    *reinterpret_cast<__half2*>(p) = __floats2half2_rn(x, y);
}

template<bool TA, bool TB, typename OutT, bool EXPSUM, bool RSCALE, bool QKV3>
__global__ __launch_bounds__(256, 2) void hgemm_kernel(
    const __half* __restrict__ Ab, const __half* __restrict__ Bb, OutT* __restrict__ Cb,
    int K, int lda, int ldb, int ldc,
    long sA, long sB, long sC,
    const float* __restrict__ bias, float alpha,
    const float* __restrict__ resid, long sR,
    float* __restrict__ rsum)
{
    extern __shared__ __align__(128) char sm[];
    const uint32_t smb = smem_u32(sm);

    const int tid = threadIdx.x;
    const int bz = blockIdx.z;
    const __half* A;
    const __half* B;
    OutT* C;
    const float* biasp = bias;
    if (QKV3) {
        const int mat = bz >> 3;
        const int b   = bz & 7;
        A = Ab + (long)mat * sA;
        B = Bb + (long)b * sB;
        C = Cb + (long)bz * sC;
        biasp = bias + mat * C_;
    } else {
        A = Ab + (long)bz * sA;
        B = Bb + (long)bz * sB;
        C = Cb + (long)bz * sC;
    }
    const int m0 = blockIdx.y * BM;
    const int n0 = blockIdx.x * BN;

    const int wid = tid >> 5, lane = tid & 31;
    const int wm = (wid & 1) * 64;
    const int wn = (wid >> 1) * 32;

    float acc[4][4][4] = {};

    auto stage = [&](int k0, int buf) {
        const uint32_t ab = smb + buf * STG_BYTES;
        const uint32_t bb = ab + 16384;
        #pragma unroll
        for (int i = 0; i < 4; i++) {
            const int c = tid + i * 256;
            if (!TA) {
                const int row = c >> 3, ch = c & 7;
                const int sw = ch ^ (row & 7);
                cp16(ab + row * 128 + sw * 16,
                     &A[(long)(m0 + row) * lda + k0 + ch * 8]);
            } else {
                const int row = c >> 4, ch = c & 15;
                const int sw = (ch & 8) | ((ch ^ row) & 7);
                cp16(ab + row * 256 + sw * 16,
                     &A[(long)(k0 + row) * lda + m0 + ch * 8]);
            }
        }
        #pragma unroll
        for (int i = 0; i < 4; i++) {
            const int c = tid + i * 256;
            if (!TB) {
                const int row = c >> 4, ch = c & 15;
                const int sw = (ch & 8) | ((ch ^ row) & 7);
                cp16(bb + row * 256 + sw * 16,
                     &B[(long)(k0 + row) * ldb + n0 + ch * 8]);
            } else {
                const int row = c >> 3, ch = c & 7;
                const int sw = ch ^ (row & 7);
                cp16(bb + row * 128 + sw * 16,
                     &B[(long)(n0 + row) * ldb + k0 + ch * 8]);
            }
        }
        cp_commit();
    };

    // fragment loader for one ks step (16 wide)
    auto load_frags = [&](int ks, uint32_t a[4][4], uint32_t b[4][2],
                          uint32_t ab, uint32_t bb) {
        #pragma unroll
        for (int mt = 0; mt < 4; mt++) {
            if (!TA) {
                const int row = wm + mt * 16 + (lane & 15);
                const int ch = (ks >> 3) + (lane >> 4);
                const int sw = ch ^ (row & 7);
                ldsm4(a[mt], ab + row * 128 + sw * 16);
            } else {
                const int kk = ks + (lane >> 4) * 8 + (lane & 7);
                const int mm = wm + mt * 16 + ((lane >> 3) & 1) * 8;
                const int ch = mm >> 3;
                const int sw = (ch & 8) | ((ch ^ kk) & 7);
                ldsm4t(a[mt], ab + kk * 256 + sw * 16);
            }
        }
        #pragma unroll
        for (int nt2 = 0; nt2 < 2; nt2++) {
            uint32_t r[4];
            if (!TB) {
                const int kk = ks + ((lane >> 3) & 1) * 8 + (lane & 7);
                const int ncol = wn + nt2 * 16 + ((lane >> 4) & 1) * 8;
                const int ch = ncol >> 3;
                const int sw = (ch & 8) | ((ch ^ kk) & 7);
                ldsm4t(r, bb + kk * 256 + sw * 16);
            } else {
                const int nn = wn + nt2 * 16 + ((lane >> 4) & 1) * 8 + (lane & 7);
                const int ch = (ks >> 3) + ((lane >> 3) & 1);
                const int sw = ch ^ (nn & 7);
                ldsm4(r, bb + nn * 128 + sw * 16);
            }
            b[2*nt2][0] = r[0]; b[2*nt2][1] = r[1];
            b[2*nt2+1][0] = r[2]; b[2*nt2+1][1] = r[3];
        }
    };

    stage(0, 0);
    stage(BK, 1);

    const int T = K / BK;
    for (int t = 0; t < T; t++) {
        cp_wait1();
        __syncthreads();
        if (t + 2 < T) stage((t + 2) * BK, (t + 2) % NSTAGE);

        const uint32_t ab = smb + (t % NSTAGE) * STG_BYTES;
        const uint32_t bb = ab + 16384;

        uint32_t fa[2][4][4], fb[2][4][2];
        load_frags(0, fa[0], fb[0], ab, bb);
        #pragma unroll
        for (int s4 = 0; s4 < 4; s4++) {
            const int cur = s4 & 1, nxt = cur ^ 1;
            if (s4 < 3) load_frags((s4 + 1) * 16, fa[nxt], fb[nxt], ab, bb);
            #pragma unroll
            for (int mt = 0; mt < 4; mt++)
                #pragma unroll
                for (int nt = 0; nt < 4; nt++)
                    mma16816(acc[mt][nt], fa[cur][mt], fb[cur][nt]);
        }
    }
    cp_wait0();

    // ---- epilogue ----
    const int r0 = m0 + wm + (lane >> 2);
    const int c0 = n0 + wn + (lane & 3) * 2;
    if (EXPSUM) {
        // alpha pre-scaled by log2(e); exp(x-8) = exp2(x*log2e - 8*log2e).
        // f16x2 MUFU: compute arg in fp32, pack to half2, single h2exp2.
        #pragma unroll
        for (int mt = 0; mt < 4; mt++) {
            #pragma unroll
            for (int h = 0; h < 2; h++) {
                const int rr = r0 + mt * 16 + h * 8;
                float rsl = 0.f;
                #pragma unroll
                for (int nt = 0; nt < 4; nt++) {
                    const float* a4 = acc[mt][nt];
                    const float ax = fmaf(a4[h*2+0], alpha, -11.541560327111708f);
                    const float ay = fmaf(a4[h*2+1], alpha, -11.541560327111708f);
                    const __half2 ev = h2exp2(__floats2half2_rn(ax, ay));
                    *reinterpret_cast<__half2*>(&C[(long)rr * ldc + c0 + nt * 8]) = ev;
                    const float2 ef = __half22float2(ev);
                    rsl += ef.x + ef.y;
                }
                rsl += __shfl_xor_sync(0xFFFFFFFFu, rsl, 1);
                rsl += __shfl_xor_sync(0xFFFFFFFFu, rsl, 2);
                if ((lane & 3) == 0)
                    atomicAdd(&rsum[(long)bz * H_ + rr], rsl);
            }
        }
    } else {
        #pragma unroll
        for (int mt = 0; mt < 4; mt++) {
            #pragma unroll
            for (int nt = 0; nt < 4; nt++) {
                const float* a4 = acc[mt][nt];
                const int c = c0 + nt * 8;
                float sx = 1.f, sy = 1.f;
                if (RSCALE) {
                    sx = __fdividef(1.f, rsum[(long)bz * H_ + c]);
                    sy = __fdividef(1.f, rsum[(long)bz * H_ + c + 1]);
                }
                #pragma unroll
                for (int h = 0; h < 2; h++) {
                    const int rr = r0 + mt * 16 + h * 8;
                    const float bi = biasp ? biasp[rr] : 0.f;
                    float vx = fmaf(a4[h * 2 + 0], alpha, bi) * sx;
                    float vy = fmaf(a4[h * 2 + 1], alpha, bi) * sy;
                    const long off = (long)rr * ldc + c;
                    if (resid) {
                        const float2 rv = *reinterpret_cast<const float2*>(&resid[(long)bz * sR + off]);
                        vx += rv.x; vy += rv.y;
                    }
                    store2(&C[off], vx, vy);
                }
            }
        }
    }
}

// ---------------------------------------------------------------------------
extern "C" void kernel_launch(void* const* d_in, const int* in_sizes, int n_in,
                              void* d_out, int out_size)
{
    const float* x     = (const float*)d_in[0];
    const float* gamma = (const float*)d_in[1];
    const float* beta  = (const float*)d_in[2];
    const float* wq    = (const float*)d_in[3];
    const float* bq    = (const float*)d_in[4];
    const float* wk    = (const float*)d_in[5];
    const float* bk    = (const float*)d_in[6];
    const float* wv    = (const float*)d_in[7];
    const float* bv    = (const float*)d_in[8];
    const float* wp    = (const float*)d_in[9];
    const float* bp    = (const float*)d_in[10];
    float* out = (float*)d_out;

    __half *hn, *qkv, *s, *w, *wph;
    float *rsum, *biasf;
    cudaGetSymbolAddress((void**)&hn,  g_hn);
    cudaGetSymbolAddress((void**)&qkv, g_qkv);
    cudaGetSymbolAddress((void**)&s,   g_s);
    cudaGetSymbolAddress((void**)&w,   g_w);
    cudaGetSymbolAddress((void**)&wph, g_wp);
    cudaGetSymbolAddress((void**)&rsum, g_rsum);
    cudaGetSymbolAddress((void**)&biasf, g_bias);

    const long HH = (long)H_ * H_;
    const long CC = (long)C_ * C_;
    const float scale = 0.044194173824159216f;            // 1/sqrt(512)
    const float scale2 = scale * 1.4426950408889634f;     // * log2(e)

    cudaFuncSetAttribute((const void*)hgemm_kernel<false, false, __half, false, false, true >, cudaFuncAttributeMaxDynamicSharedMemorySize, GEMM_SMEM);
    cudaFuncSetAttribute((const void*)hgemm_kernel<false, false, float,  false, false, false>, cudaFuncAttributeMaxDynamicSharedMemorySize, GEMM_SMEM);
    cudaFuncSetAttribute((const void*)hgemm_kernel<true,  false, __half, true,  false, false>, cudaFuncAttributeMaxDynamicSharedMemorySize, GEMM_SMEM);
    cudaFuncSetAttribute((const void*)hgemm_kernel<false, true,  __half, false, true,  false>, cudaFuncAttributeMaxDynamicSharedMemorySize, GEMM_SMEM);

    // 0. fused prep: GN (blocks 0-255) + weight conversion (blocks 256-1279)
    prep_kernel<<<1280, 256>>>(x, gamma, beta, hn, wq, wk, wv, wp, bq, bk, bv);

    // 1. fused q/k/v: grid.z = mat*8+b  -> g_qkv[mat][b][C][H]
    dim3 gqkv(H_ / BN, C_ / BM, 24);
    hgemm_kernel<false, false, __half, false, false, true><<<gqkv, 256, GEMM_SMEM>>>(
        w, hn, qkv, C_, C_, H_, H_, CC, CH, CH, biasf, 1.f, nullptr, 0, nullptr);

    const __half* qp = qkv;                 // mat 0
    const __half* kp = qkv + 8 * CH;        // mat 1
    const __half* vp = qkv + 16 * CH;       // mat 2

    // 2. P[b,i,j] = exp(scale * sum_c q[b,c,i] k[b,c,j] - 8), rowsum -> rsum
    dim3 gsc(H_ / BN, H_ / BM, B_);
    hgemm_kernel<true, false, __half, true, false, false><<<gsc, 256, GEMM_SMEM>>>(
        qp, kp, s, C_, H_, H_, H_, CH, CH, HH, nullptr, scale2, nullptr, 0, rsum);

    // 3. h_[b,c,i] = (1/rsum[i]) * sum_j v[b,c,j] P[i,j]   (A=[m,k], B=[n,k])
    dim3 gav(H_ / BN, C_ / BM, B_);
    hgemm_kernel<false, true, __half, false, true, false><<<gav, 256, GEMM_SMEM>>>(
        vp, s, hn, H_, H_, H_, H_, CH, HH, CH, nullptr, 1.f, nullptr, 0, rsum);

    // 4. out = x + Wp @ h_ + bp  (fp32 out, residual)
    dim3 gpr(H_ / BN, C_ / BM, B_);
    hgemm_kernel<false, false, float, false, false, false><<<gpr, 256, GEMM_SMEM>>>(
        wph, hn, out, C_, C_, H_, H_, 0, CH, CH, bp, 1.f, x, CH, nullptr);
}